// round 6
// baseline (speedup 1.0000x reference)
#include <cuda_runtime.h>
#include <cuda_bf16.h>
#include <cstdint>
#include <math.h>

// ---------------- problem constants ----------------
#define BSZ   2
#define LQ    17821
#define CDIM  256
#define MTOK  (BSZ*LQ)          // 35642
#define MPAD  35712             // 279 * 128
#define MT128 279
#define DFFN  1024
#define PAD   72                // smem row stride in halves (144B, conflict-free)

__device__ __constant__ int c_H[4]  = {100, 50, 25, 13};
__device__ __constant__ int c_W[4]  = {134, 67, 34, 17};
__device__ __constant__ int c_st[4] = {0, 13400, 16750, 17600};

// ---------------- scratch (no allocs; zero-initialized .bss) ----------------
__device__ __nv_bfloat16 g_nb    [(size_t)MPAD*CDIM];
__device__ __nv_bfloat16 g_qb    [(size_t)MPAD*CDIM];
__device__ __nv_bfloat16 g_valueb[(size_t)MPAD*CDIM];
__device__ float         g_off   [(size_t)MTOK*CDIM];
__device__ float         g_awl   [(size_t)MTOK*128];
__device__ __nv_bfloat16 g_attnb [(size_t)MPAD*CDIM];
__device__ float         g_x     [(size_t)MTOK*CDIM];
__device__ __nv_bfloat16 g_n2b   [(size_t)MPAD*CDIM];
__device__ __nv_bfloat16 g_hb    [(size_t)MPAD*DFFN];
// converted weights: Wv,Woff,Waw,Wo,FFint(W1/W2 row-interleaved),W3
#define WOFF_WV   0
#define WOFF_WOFF 65536
#define WOFF_WAW  131072
#define WOFF_WO   163840
#define WOFF_FF   229376
#define WOFF_W3   753664
__device__ __nv_bfloat16 g_wb[1015808];

// ================= helpers =================
__device__ __forceinline__ uint32_t smem_u32(const void* p) {
    uint32_t a;
    asm("{ .reg .u64 t; cvta.to.shared.u64 t, %1; cvt.u32.u64 %0, t; }" : "=r"(a) : "l"(p));
    return a;
}
__device__ __forceinline__ void ldsm4(uint32_t* r, uint32_t addr) {
    asm volatile("ldmatrix.sync.aligned.m8n8.x4.shared.b16 {%0,%1,%2,%3}, [%4];"
        : "=r"(r[0]), "=r"(r[1]), "=r"(r[2]), "=r"(r[3]) : "r"(addr));
}
__device__ __forceinline__ void mma_bf16(float* c, const uint32_t* a, const uint32_t* b) {
    asm volatile(
        "mma.sync.aligned.m16n8k16.row.col.f32.bf16.bf16.f32 "
        "{%0,%1,%2,%3}, {%4,%5,%6,%7}, {%8,%9}, {%0,%1,%2,%3};"
        : "+f"(c[0]), "+f"(c[1]), "+f"(c[2]), "+f"(c[3])
        : "r"(a[0]), "r"(a[1]), "r"(a[2]), "r"(a[3]), "r"(b[0]), "r"(b[1]));
}
__device__ __forceinline__ void cp16(uint32_t dst, const void* src) {
    asm volatile("cp.async.ca.shared.global [%0], [%1], 16;" :: "r"(dst), "l"(src));
}
#define CP_COMMIT() asm volatile("cp.async.commit_group;" ::: "memory")
#define CP_WAIT1()  asm volatile("cp.async.wait_group 1;" ::: "memory")
#define CP_WAIT0()  asm volatile("cp.async.wait_group 0;" ::: "memory")

// ---------------- weight fp32 -> bf16 convert (W1/W2 interleaved) ----------------
struct WSrc { const float* s[7]; };
__device__ __constant__ int c_wsz [7] = {65536, 65536, 32768, 65536, 262144, 262144, 262144};
__device__ __constant__ int c_woff[7] = {WOFF_WV, WOFF_WOFF, WOFF_WAW, WOFF_WO, WOFF_FF, WOFF_FF, WOFF_W3};

__global__ void __launch_bounds__(256) wconv_kernel(WSrc w) {
    int seg = blockIdx.y;
    int i = (blockIdx.x * 256 + threadIdx.x) * 4;
    if (i >= c_wsz[seg]) return;
    float4 v = *(const float4*)(w.s[seg] + i);
    __nv_bfloat16* d;
    if (seg == 4 || seg == 5) {
        // W1 -> even rows, W2 -> odd rows of FFint (2048 x 256)
        int row = i >> 8, col = i & 255;
        d = g_wb + WOFF_FF + (size_t)((row << 1) + (seg - 4)) * 256 + col;
    } else {
        d = g_wb + c_woff[seg] + i;
    }
    *(__nv_bfloat162*)(d)     = __floats2bfloat162_rn(v.x, v.y);
    *(__nv_bfloat162*)(d + 2) = __floats2bfloat162_rn(v.z, v.w);
}

// ---------------- RMSNorm -> bf16 (+ optional bf16 normed+addend) ----------------
__global__ void __launch_bounds__(256) rmsnorm_kernel(
    const float* __restrict__ x, const float* __restrict__ w,
    __nv_bfloat16* __restrict__ out, const float* __restrict__ addend,
    __nv_bfloat16* __restrict__ out2)
{
    int row  = blockIdx.x * 8 + (threadIdx.x >> 5);
    if (row >= MTOK) return;
    int lane = threadIdx.x & 31;
    const float4* xr = (const float4*)(x + (size_t)row * CDIM);
    float4 v0 = xr[lane];
    float4 v1 = xr[lane + 32];
    float ss = v0.x*v0.x + v0.y*v0.y + v0.z*v0.z + v0.w*v0.w
             + v1.x*v1.x + v1.y*v1.y + v1.z*v1.z + v1.w*v1.w;
    #pragma unroll
    for (int o = 16; o > 0; o >>= 1) ss += __shfl_xor_sync(0xffffffffu, ss, o);
    float s = rsqrtf(ss * (1.0f / CDIM) + 1e-6f);
    const float4* w4 = (const float4*)w;
    float4 g0 = w4[lane], g1 = w4[lane + 32];
    float n0x = v0.x*s*g0.x, n0y = v0.y*s*g0.y, n0z = v0.z*s*g0.z, n0w = v0.w*s*g0.w;
    float n1x = v1.x*s*g1.x, n1y = v1.y*s*g1.y, n1z = v1.z*s*g1.z, n1w = v1.w*s*g1.w;
    __nv_bfloat162* o2 = (__nv_bfloat162*)(out + (size_t)row * CDIM);
    o2[lane*2+0]  = __floats2bfloat162_rn(n0x, n0y);
    o2[lane*2+1]  = __floats2bfloat162_rn(n0z, n0w);
    o2[64+lane*2] = __floats2bfloat162_rn(n1x, n1y);
    o2[65+lane*2] = __floats2bfloat162_rn(n1z, n1w);
    if (out2) {
        const float4* a4 = (const float4*)(addend + (size_t)row * CDIM);
        float4 p0 = a4[lane], p1 = a4[lane + 32];
        __nv_bfloat162* q2 = (__nv_bfloat162*)(out2 + (size_t)row * CDIM);
        q2[lane*2+0]  = __floats2bfloat162_rn(n0x + p0.x, n0y + p0.y);
        q2[lane*2+1]  = __floats2bfloat162_rn(n0z + p0.z, n0w + p0.w);
        q2[64+lane*2] = __floats2bfloat162_rn(n1x + p1.x, n1y + p1.y);
        q2[65+lane*2] = __floats2bfloat162_rn(n1z + p1.z, n1w + p1.w);
    }
}

// ---------------- HMMA GEMM: CTA 128x128, 4 warps (64x64 each), 3-stage cp.async ----
// out[m,n] = sum_k A[m,k]*B[n,k] + bias[n]. Modes:
//  - swiglu=1: B is interleaved [W1;W2]; pair (even,odd) -> silu(z1)*z2 -> outb[m, n/2]
//  - split:    n < N1 -> outp (+bias, optional residual/gain, optional bf16 outb)
//              n >= N1 -> outp2 (stride N-N1, bias2)
#define TILE_BYTES  (128 * PAD * 2)     // 18432
#define STAGE_BYTES (2 * TILE_BYTES)    // 36864: [As | Bs]
#define NSTAGE 3

__global__ void __launch_bounds__(128) hmma_gemm_kernel(
    const __nv_bfloat16* __restrict__ A, const __nv_bfloat16* __restrict__ B,
    const float* __restrict__ bias, const float* __restrict__ bias2,
    float* __restrict__ outp, float* __restrict__ outp2,
    __nv_bfloat16* __restrict__ outb,
    int M, int N, int N1, int K, int swiglu,
    const float* __restrict__ residual, const float* __restrict__ gain)
{
    extern __shared__ __align__(16) char smem[];
    uint32_t sb = smem_u32(smem);
    int tid = threadIdx.x, lane = tid & 31, wid = tid >> 5;
    int m0 = blockIdx.y * 128, n0 = blockIdx.x * 128;
    int warp_m = (wid & 1) * 64, warp_n = (wid >> 1) * 64;

    float acc[4][8][4] = {};

    int sub = lane >> 3, lrow = lane & 7;
    uint32_t a_off = ((warp_m + (sub & 1) * 8 + lrow) * PAD + (sub >> 1) * 8) * 2;
    uint32_t b_off = TILE_BYTES + ((warp_n + (sub >> 1) * 8 + lrow) * PAD + (sub & 1) * 8) * 2;

    const int NCH = K >> 6;
    const int ld4 = K >> 3;
    int lrow4 = tid >> 3, lcol4 = tid & 7;  // rows lrow4 + p*16, p=0..7
    const uint4* agl = (const uint4*)(A + (size_t)m0 * K) + (size_t)lrow4 * ld4 + lcol4;
    const uint4* bgl = (const uint4*)(B + (size_t)n0 * K) + (size_t)lrow4 * ld4 + lcol4;
    uint32_t sdst = sb + lrow4 * (PAD * 2) + lcol4 * 16;

    // prologue: stages 0,1
    #pragma unroll
    for (int s = 0; s < 2; s++) {
        if (s < NCH) {
            uint32_t d = sdst + s * STAGE_BYTES;
            const uint4* ag = agl + (size_t)s * 8;
            const uint4* bg = bgl + (size_t)s * 8;
            #pragma unroll
            for (int p = 0; p < 8; p++) {
                cp16(d + p * 16 * (PAD * 2),              ag + (size_t)p * 16 * ld4);
                cp16(d + TILE_BYTES + p * 16 * (PAD * 2), bg + (size_t)p * 16 * ld4);
            }
        }
        CP_COMMIT();
    }

    int stage = 0, lstage = 2;
    for (int c = 0; c < NCH; c++) {
        if (c + 1 < NCH) CP_WAIT1(); else CP_WAIT0();
        __syncthreads();
        if (c + 2 < NCH) {
            uint32_t d = sdst + lstage * STAGE_BYTES;
            const uint4* ag = agl + (size_t)(c + 2) * 8;
            const uint4* bg = bgl + (size_t)(c + 2) * 8;
            #pragma unroll
            for (int p = 0; p < 8; p++) {
                cp16(d + p * 16 * (PAD * 2),              ag + (size_t)p * 16 * ld4);
                cp16(d + TILE_BYTES + p * 16 * (PAD * 2), bg + (size_t)p * 16 * ld4);
            }
            CP_COMMIT();
            if (++lstage == NSTAGE) lstage = 0;
        }
        uint32_t ab = sb + stage * STAGE_BYTES + a_off;
        uint32_t bb = sb + stage * STAGE_BYTES + b_off;
        #pragma unroll
        for (int ks = 0; ks < 4; ks++) {
            uint32_t af[4][4], bf[4][4];
            #pragma unroll
            for (int mt = 0; mt < 4; mt++) ldsm4(af[mt], ab + (mt * 16 * PAD + ks * 16) * 2);
            #pragma unroll
            for (int pr = 0; pr < 4; pr++) ldsm4(bf[pr], bb + (pr * 16 * PAD + ks * 16) * 2);
            #pragma unroll
            for (int mt = 0; mt < 4; mt++) {
                #pragma unroll
                for (int pr = 0; pr < 4; pr++) {
                    mma_bf16(acc[mt][2*pr+0], af[mt], &bf[pr][0]);
                    mma_bf16(acc[mt][2*pr+1], af[mt], &bf[pr][2]);
                }
            }
        }
        if (++stage == NSTAGE) stage = 0;
    }

    int crow = lane >> 2, ccol = (lane & 3) * 2;
    int Nh = N >> 1;
    #pragma unroll
    for (int mt = 0; mt < 4; mt++) {
        #pragma unroll
        for (int half = 0; half < 2; half++) {
            int m = m0 + warp_m + mt * 16 + crow + half * 8;
            if (m >= M) continue;
            #pragma unroll
            for (int nt = 0; nt < 8; nt++) {
                int n = n0 + warp_n + nt * 8 + ccol;
                float vx = acc[mt][nt][half * 2 + 0];
                float vy = acc[mt][nt][half * 2 + 1];
                if (swiglu) {
                    int n2 = n >> 1;
                    float z = vx + bias[n2];
                    float g = vy + bias2[n2];
                    float h = (z / (1.0f + __expf(-z))) * g;
                    outb[(size_t)m * Nh + n2] = __float2bfloat16(h);
                } else if (n < N1) {
                    vx += bias[n]; vy += bias[n + 1];
                    if (residual) {
                        float2 rr = *(const float2*)(residual + (size_t)m * N1 + n);
                        vx = rr.x + gain[n]     * vx;
                        vy = rr.y + gain[n + 1] * vy;
                    }
                    if (outb) {
                        *(__nv_bfloat162*)(outb + (size_t)m * N1 + n) = __floats2bfloat162_rn(vx, vy);
                    } else {
                        *(float2*)(outp + (size_t)m * N1 + n) = make_float2(vx, vy);
                    }
                } else {
                    int S2 = N - N1, n2 = n - N1;
                    vx += bias2[n2]; vy += bias2[n2 + 1];
                    *(float2*)(outp2 + (size_t)m * S2 + n2) = make_float2(vx, vy);
                }
            }
        }
    }
}

// ---------------- deformable-attention sampling ----------------
// 2 tokens/block; warp handles (token, head-pair); 16 lanes/head, bf16x2 channels.
__global__ void __launch_bounds__(256) msda_kernel(
    const float* __restrict__ ref,
    const __nv_bfloat16* __restrict__ value,
    const float* __restrict__ off,
    const float* __restrict__ awl,
    __nv_bfloat16* __restrict__ outp)
{
    int tid   = threadIdx.x;
    int wid   = tid >> 5, lane = tid & 31;
    int token = blockIdx.x * 2 + (wid >> 2);
    int h     = ((wid & 3) << 1) + (lane >> 4);
    int ch2   = lane & 15;

    const float* aw = awl + (size_t)token * 128 + h * 16;
    const float* of = off + (size_t)token * 256 + h * 32;

    float wgt[16];
    float mx = -1e30f;
    #pragma unroll
    for (int s = 0; s < 16; s++) { wgt[s] = aw[s]; mx = fmaxf(mx, wgt[s]); }
    float sum = 0.f;
    #pragma unroll
    for (int s = 0; s < 16; s++) { wgt[s] = __expf(wgt[s] - mx); sum += wgt[s]; }
    float inv = 1.0f / sum;

    int b = token / LQ;
    const __nv_bfloat162* vb = (const __nv_bfloat162*)value + (size_t)b * LQ * 128 + h * 16 + ch2;

    float ax = 0.f, ay = 0.f;
    #pragma unroll
    for (int l = 0; l < 4; l++) {
        const int H  = c_H[l];
        const int W  = c_W[l];
        const int st = c_st[l];
        float rx = ref[(size_t)token * 8 + l * 2 + 0];
        float ry = ref[(size_t)token * 8 + l * 2 + 1];
        #pragma unroll
        for (int p = 0; p < 4; p++) {
            int s = l * 4 + p;
            float x = fmaf(rx, (float)W, of[s * 2 + 0] - 0.5f);
            float y = fmaf(ry, (float)H, of[s * 2 + 1] - 0.5f);
            float x0f = floorf(x), y0f = floorf(y);
            int   x0  = (int)x0f,  y0  = (int)y0f;
            float lx = x - x0f, ly = y - y0f;
            float ws  = wgt[s] * inv;
            float w00 = (1.f - lx) * (1.f - ly) * ws;
            float w01 = lx * (1.f - ly) * ws;
            float w10 = (1.f - lx) * ly * ws;
            float w11 = lx * ly * ws;
            bool x0v = (x0 >= 0)     && (x0 < W);
            bool x1v = (x0 + 1 >= 0) && (x0 + 1 < W);
            if (y0 >= 0 && y0 < H) {
                long long base = (long long)(st + y0 * W) * 128;
                if (x0v) { float2 f = __bfloat1622float2(vb[base + (long long)x0 * 128]);
                           ax += w00 * f.x; ay += w00 * f.y; }
                if (x1v) { float2 f = __bfloat1622float2(vb[base + (long long)(x0 + 1) * 128]);
                           ax += w01 * f.x; ay += w01 * f.y; }
            }
            int y1 = y0 + 1;
            if (y1 >= 0 && y1 < H) {
                long long base = (long long)(st + y1 * W) * 128;
                if (x0v) { float2 f = __bfloat1622float2(vb[base + (long long)x0 * 128]);
                           ax += w10 * f.x; ay += w10 * f.y; }
                if (x1v) { float2 f = __bfloat1622float2(vb[base + (long long)(x0 + 1) * 128]);
                           ax += w11 * f.x; ay += w11 * f.y; }
            }
        }
    }
    *(__nv_bfloat162*)(outp + (size_t)token * 256 + h * 32 + ch2 * 2) = __floats2bfloat162_rn(ax, ay);
}

// ---------------- host launch ----------------
template <typename T>
static T* symaddr(const void* sym) {
    void* p = nullptr;
    cudaGetSymbolAddress(&p, sym);
    return (T*)p;
}

extern "C" void kernel_launch(void* const* d_in, const int* in_sizes, int n_in,
                              void* d_out, int out_size) {
    (void)in_sizes; (void)n_in; (void)out_size;
    const float* query = (const float*)d_in[0];
    const float* qpos  = (const float*)d_in[1];
    const float* ref   = (const float*)d_in[2];
    const float* nw1   = (const float*)d_in[5];
    const float* Wv    = (const float*)d_in[6];
    const float* bv    = (const float*)d_in[7];
    const float* Woff  = (const float*)d_in[8];
    const float* boff  = (const float*)d_in[9];
    const float* Waw   = (const float*)d_in[10];
    const float* baw   = (const float*)d_in[11];
    const float* Wo    = (const float*)d_in[12];
    const float* bo    = (const float*)d_in[13];
    const float* lsa   = (const float*)d_in[14];
    const float* nw2   = (const float*)d_in[15];
    const float* W1    = (const float*)d_in[16];
    const float* b1    = (const float*)d_in[17];
    const float* W2    = (const float*)d_in[18];
    const float* b2    = (const float*)d_in[19];
    const float* W3    = (const float*)d_in[20];
    const float* b3    = (const float*)d_in[21];
    const float* lsf   = (const float*)d_in[22];
    float* out = (float*)d_out;

    __nv_bfloat16* nb    = symaddr<__nv_bfloat16>(g_nb);
    __nv_bfloat16* qb    = symaddr<__nv_bfloat16>(g_qb);
    __nv_bfloat16* valb  = symaddr<__nv_bfloat16>(g_valueb);
    float*         poff  = symaddr<float>(g_off);
    float*         pawl  = symaddr<float>(g_awl);
    __nv_bfloat16* attnb = symaddr<__nv_bfloat16>(g_attnb);
    float*         px    = symaddr<float>(g_x);
    __nv_bfloat16* n2b   = symaddr<__nv_bfloat16>(g_n2b);
    __nv_bfloat16* hb    = symaddr<__nv_bfloat16>(g_hb);
    __nv_bfloat16* wb    = symaddr<__nv_bfloat16>(g_wb);

    const int GSM = NSTAGE * STAGE_BYTES;   // 110592
    cudaFuncSetAttribute(hmma_gemm_kernel, cudaFuncAttributeMaxDynamicSharedMemorySize, GSM);

    // 0. weights -> bf16 (W1/W2 interleaved)
    WSrc ws; ws.s[0] = Wv; ws.s[1] = Woff; ws.s[2] = Waw; ws.s[3] = Wo;
    ws.s[4] = W1; ws.s[5] = W2; ws.s[6] = W3;
    wconv_kernel<<<dim3(256, 7), 256>>>(ws);

    // 1. rmsnorm -> normed bf16, q = normed+pos bf16
    rmsnorm_kernel<<<(MTOK + 7) / 8, 256>>>(query, nw1, nb, qpos, qb);
    // 2. value = normed @ Wv^T + bv  (bf16 out)
    hmma_gemm_kernel<<<dim3(2, MT128), 128, GSM>>>(nb, wb + WOFF_WV, bv, nullptr,
        nullptr, nullptr, valb, MTOK, 256, 256, 256, 0, nullptr, nullptr);
    // 3. fused offsets+logits: q @ [Woff;Waw]^T, split outputs
    hmma_gemm_kernel<<<dim3(3, MT128), 128, GSM>>>(qb, wb + WOFF_WOFF, boff, baw,
        poff, pawl, nullptr, MTOK, 384, 256, 256, 0, nullptr, nullptr);
    // 4. deformable sampling -> attn bf16
    msda_kernel<<<MTOK / 2, 256>>>(ref, valb, poff, pawl, attnb);
    // 5. x = query + ls_attn * (attn @ Wo^T + bo)
    hmma_gemm_kernel<<<dim3(2, MT128), 128, GSM>>>(attnb, wb + WOFF_WO, bo, nullptr,
        px, nullptr, nullptr, MTOK, 256, 256, 256, 0, query, lsa);
    // 6. n2 = rmsnorm(x) bf16
    rmsnorm_kernel<<<(MTOK + 7) / 8, 256>>>(px, nw2, n2b, nullptr, nullptr);
    // 7. FFN-up (interleaved W1/W2, swiglu epilogue) -> h bf16
    hmma_gemm_kernel<<<dim3(16, MT128), 128, GSM>>>(n2b, wb + WOFF_FF, b1, b2,
        nullptr, nullptr, hb, MTOK, 2048, 2048, 256, 1, nullptr, nullptr);
    // 8. out = x + ls_ffn * (h @ W3^T + b3)
    hmma_gemm_kernel<<<dim3(2, MT128), 128, GSM>>>(hb, wb + WOFF_W3, b3, nullptr,
        out, nullptr, nullptr, MTOK, 256, 256, 1024, 0, px, lsf);
}

// round 7
// speedup vs baseline: 1.0964x; 1.0964x over previous
#include <cuda_runtime.h>
#include <cuda_bf16.h>
#include <cstdint>
#include <math.h>

// ---------------- problem constants ----------------
#define BSZ   2
#define LQ    17821
#define CDIM  256
#define MTOK  (BSZ*LQ)          // 35642
#define MPAD  35712             // 279 * 128
#define MT128 279
#define DFFN  1024
#define PAD   72                // smem row stride in halves (144B, conflict-free)

__device__ __constant__ int c_H[4]  = {100, 50, 25, 13};
__device__ __constant__ int c_W[4]  = {134, 67, 34, 17};
__device__ __constant__ int c_st[4] = {0, 13400, 16750, 17600};

// ---------------- scratch (no allocs; zero-initialized .bss) ----------------
__device__ __nv_bfloat16 g_nb    [(size_t)MPAD*CDIM];
__device__ __nv_bfloat16 g_qb    [(size_t)MPAD*CDIM];
__device__ __nv_bfloat16 g_valueb[(size_t)MPAD*CDIM];
__device__ float         g_off   [(size_t)MTOK*CDIM];
__device__ float         g_awl   [(size_t)MTOK*128];
__device__ __nv_bfloat16 g_attnb [(size_t)MPAD*CDIM];
__device__ float         g_x     [(size_t)MTOK*CDIM];
__device__ __nv_bfloat16 g_n2b   [(size_t)MPAD*CDIM];
__device__ __nv_bfloat16 g_hb    [(size_t)MPAD*DFFN];
// converted weights: Wv,Woff,Waw,Wo,FFint(W1/W2 row-interleaved),W3
#define WOFF_WV   0
#define WOFF_WOFF 65536
#define WOFF_WAW  131072
#define WOFF_WO   163840
#define WOFF_FF   229376
#define WOFF_W3   753664
__device__ __nv_bfloat16 g_wb[1015808];

// ================= helpers =================
__device__ __forceinline__ uint32_t smem_u32(const void* p) {
    uint32_t a;
    asm("{ .reg .u64 t; cvta.to.shared.u64 t, %1; cvt.u32.u64 %0, t; }" : "=r"(a) : "l"(p));
    return a;
}
__device__ __forceinline__ void ldsm4(uint32_t* r, uint32_t addr) {
    asm volatile("ldmatrix.sync.aligned.m8n8.x4.shared.b16 {%0,%1,%2,%3}, [%4];"
        : "=r"(r[0]), "=r"(r[1]), "=r"(r[2]), "=r"(r[3]) : "r"(addr));
}
__device__ __forceinline__ void mma_bf16(float* c, const uint32_t* a, const uint32_t* b) {
    asm volatile(
        "mma.sync.aligned.m16n8k16.row.col.f32.bf16.bf16.f32 "
        "{%0,%1,%2,%3}, {%4,%5,%6,%7}, {%8,%9}, {%0,%1,%2,%3};"
        : "+f"(c[0]), "+f"(c[1]), "+f"(c[2]), "+f"(c[3])
        : "r"(a[0]), "r"(a[1]), "r"(a[2]), "r"(a[3]), "r"(b[0]), "r"(b[1]));
}
__device__ __forceinline__ void cp16(uint32_t dst, const void* src) {
    asm volatile("cp.async.ca.shared.global [%0], [%1], 16;" :: "r"(dst), "l"(src));
}
#define CP_COMMIT() asm volatile("cp.async.commit_group;" ::: "memory")
#define CP_WAIT1()  asm volatile("cp.async.wait_group 1;" ::: "memory")
#define CP_WAIT0()  asm volatile("cp.async.wait_group 0;" ::: "memory")

// ---------------- weight fp32 -> bf16 convert (W1/W2 interleaved) ----------------
struct WSrc { const float* s[7]; };
__device__ __constant__ int c_wsz [7] = {65536, 65536, 32768, 65536, 262144, 262144, 262144};
__device__ __constant__ int c_woff[7] = {WOFF_WV, WOFF_WOFF, WOFF_WAW, WOFF_WO, WOFF_FF, WOFF_FF, WOFF_W3};

__global__ void __launch_bounds__(256) wconv_kernel(WSrc w) {
    int seg = blockIdx.y;
    int i = (blockIdx.x * 256 + threadIdx.x) * 4;
    if (i >= c_wsz[seg]) return;
    float4 v = *(const float4*)(w.s[seg] + i);
    __nv_bfloat16* d;
    if (seg == 4 || seg == 5) {
        // W1 -> even rows, W2 -> odd rows of FFint (2048 x 256)
        int row = i >> 8, col = i & 255;
        d = g_wb + WOFF_FF + (size_t)((row << 1) + (seg - 4)) * 256 + col;
    } else {
        d = g_wb + c_woff[seg] + i;
    }
    *(__nv_bfloat162*)(d)     = __floats2bfloat162_rn(v.x, v.y);
    *(__nv_bfloat162*)(d + 2) = __floats2bfloat162_rn(v.z, v.w);
}

// ---------------- RMSNorm -> bf16 (+ optional bf16 normed+addend) ----------------
__global__ void __launch_bounds__(256) rmsnorm_kernel(
    const float* __restrict__ x, const float* __restrict__ w,
    __nv_bfloat16* __restrict__ out, const float* __restrict__ addend,
    __nv_bfloat16* __restrict__ out2)
{
    int row  = blockIdx.x * 8 + (threadIdx.x >> 5);
    if (row >= MTOK) return;
    int lane = threadIdx.x & 31;
    const float4* xr = (const float4*)(x + (size_t)row * CDIM);
    float4 v0 = xr[lane];
    float4 v1 = xr[lane + 32];
    float ss = v0.x*v0.x + v0.y*v0.y + v0.z*v0.z + v0.w*v0.w
             + v1.x*v1.x + v1.y*v1.y + v1.z*v1.z + v1.w*v1.w;
    #pragma unroll
    for (int o = 16; o > 0; o >>= 1) ss += __shfl_xor_sync(0xffffffffu, ss, o);
    float s = rsqrtf(ss * (1.0f / CDIM) + 1e-6f);
    const float4* w4 = (const float4*)w;
    float4 g0 = w4[lane], g1 = w4[lane + 32];
    float n0x = v0.x*s*g0.x, n0y = v0.y*s*g0.y, n0z = v0.z*s*g0.z, n0w = v0.w*s*g0.w;
    float n1x = v1.x*s*g1.x, n1y = v1.y*s*g1.y, n1z = v1.z*s*g1.z, n1w = v1.w*s*g1.w;
    __nv_bfloat162* o2 = (__nv_bfloat162*)(out + (size_t)row * CDIM);
    o2[lane*2+0]  = __floats2bfloat162_rn(n0x, n0y);
    o2[lane*2+1]  = __floats2bfloat162_rn(n0z, n0w);
    o2[64+lane*2] = __floats2bfloat162_rn(n1x, n1y);
    o2[65+lane*2] = __floats2bfloat162_rn(n1z, n1w);
    if (out2) {
        const float4* a4 = (const float4*)(addend + (size_t)row * CDIM);
        float4 p0 = a4[lane], p1 = a4[lane + 32];
        __nv_bfloat162* q2 = (__nv_bfloat162*)(out2 + (size_t)row * CDIM);
        q2[lane*2+0]  = __floats2bfloat162_rn(n0x + p0.x, n0y + p0.y);
        q2[lane*2+1]  = __floats2bfloat162_rn(n0z + p0.z, n0w + p0.w);
        q2[64+lane*2] = __floats2bfloat162_rn(n1x + p1.x, n1y + p1.y);
        q2[65+lane*2] = __floats2bfloat162_rn(n1z + p1.z, n1w + p1.w);
    }
}

// ---------------- HMMA GEMM: CTA 128x128, 8 warps (64x32 each), 3-stage cp.async ----
// out[m,n] = sum_k A[m,k]*B[n,k] + bias[n]. Modes:
//  - swiglu=1: B is interleaved [W1;W2]; pair (even,odd) -> silu(z1)*z2 -> outb[m, n/2]
//  - split:    n < N1 -> outp (+bias, optional residual/gain, optional bf16 outb)
//              n >= N1 -> outp2 (stride N-N1, bias2)
#define TILE_BYTES  (128 * PAD * 2)     // 18432
#define STAGE_BYTES (2 * TILE_BYTES)    // 36864: [As | Bs]
#define NSTAGE 3

__global__ void __launch_bounds__(256) hmma_gemm_kernel(
    const __nv_bfloat16* __restrict__ A, const __nv_bfloat16* __restrict__ B,
    const float* __restrict__ bias, const float* __restrict__ bias2,
    float* __restrict__ outp, float* __restrict__ outp2,
    __nv_bfloat16* __restrict__ outb,
    int M, int N, int N1, int K, int swiglu,
    const float* __restrict__ residual, const float* __restrict__ gain)
{
    extern __shared__ __align__(16) char smem[];
    uint32_t sb = smem_u32(smem);
    int tid = threadIdx.x, lane = tid & 31, wid = tid >> 5;
    int m0 = blockIdx.y * 128, n0 = blockIdx.x * 128;
    int warp_m = (wid & 1) * 64, warp_n = (wid >> 1) * 32;

    float acc[4][4][4] = {};

    int sub = lane >> 3, lrow = lane & 7;
    uint32_t a_off = ((warp_m + (sub & 1) * 8 + lrow) * PAD + (sub >> 1) * 8) * 2;
    uint32_t b_off = TILE_BYTES + ((warp_n + (sub >> 1) * 8 + lrow) * PAD + (sub & 1) * 8) * 2;

    const int NCH = K >> 6;
    const int ld4 = K >> 3;
    int lrow4 = tid >> 3, lcol4 = tid & 7;
    const uint4* agl = (const uint4*)(A + (size_t)m0 * K) + (size_t)lrow4 * ld4 + lcol4;
    const uint4* bgl = (const uint4*)(B + (size_t)n0 * K) + (size_t)lrow4 * ld4 + lcol4;
    uint32_t sdst = sb + lrow4 * (PAD * 2) + lcol4 * 16;

    // prologue: stages 0,1
    #pragma unroll
    for (int s = 0; s < 2; s++) {
        if (s < NCH) {
            uint32_t d = sdst + s * STAGE_BYTES;
            const uint4* ag = agl + (size_t)s * 8;
            const uint4* bg = bgl + (size_t)s * 8;
            #pragma unroll
            for (int p = 0; p < 4; p++) {
                cp16(d + p * 32 * (PAD * 2),              ag + (size_t)p * 32 * ld4);
                cp16(d + TILE_BYTES + p * 32 * (PAD * 2), bg + (size_t)p * 32 * ld4);
            }
        }
        CP_COMMIT();
    }

    int stage = 0, lstage = 2;
    for (int c = 0; c < NCH; c++) {
        if (c + 1 < NCH) CP_WAIT1(); else CP_WAIT0();
        __syncthreads();
        if (c + 2 < NCH) {
            uint32_t d = sdst + lstage * STAGE_BYTES;
            const uint4* ag = agl + (size_t)(c + 2) * 8;
            const uint4* bg = bgl + (size_t)(c + 2) * 8;
            #pragma unroll
            for (int p = 0; p < 4; p++) {
                cp16(d + p * 32 * (PAD * 2),              ag + (size_t)p * 32 * ld4);
                cp16(d + TILE_BYTES + p * 32 * (PAD * 2), bg + (size_t)p * 32 * ld4);
            }
            CP_COMMIT();
            if (++lstage == NSTAGE) lstage = 0;
        }
        uint32_t ab = sb + stage * STAGE_BYTES + a_off;
        uint32_t bb = sb + stage * STAGE_BYTES + b_off;
        #pragma unroll
        for (int ks = 0; ks < 4; ks++) {
            uint32_t af[4][4], bf[2][4];
            #pragma unroll
            for (int mt = 0; mt < 4; mt++) ldsm4(af[mt], ab + (mt * 16 * PAD + ks * 16) * 2);
            #pragma unroll
            for (int pr = 0; pr < 2; pr++) ldsm4(bf[pr], bb + (pr * 16 * PAD + ks * 16) * 2);
            #pragma unroll
            for (int mt = 0; mt < 4; mt++) {
                mma_bf16(acc[mt][0], af[mt], &bf[0][0]);
                mma_bf16(acc[mt][1], af[mt], &bf[0][2]);
                mma_bf16(acc[mt][2], af[mt], &bf[1][0]);
                mma_bf16(acc[mt][3], af[mt], &bf[1][2]);
            }
        }
        if (++stage == NSTAGE) stage = 0;
    }

    int crow = lane >> 2, ccol = (lane & 3) * 2;
    int Nh = N >> 1;
    #pragma unroll
    for (int mt = 0; mt < 4; mt++) {
        #pragma unroll
        for (int half = 0; half < 2; half++) {
            int m = m0 + warp_m + mt * 16 + crow + half * 8;
            if (m >= M) continue;
            #pragma unroll
            for (int nt = 0; nt < 4; nt++) {
                int n = n0 + warp_n + nt * 8 + ccol;
                float vx = acc[mt][nt][half * 2 + 0];
                float vy = acc[mt][nt][half * 2 + 1];
                if (swiglu) {
                    int j = n >> 1;   // n even: (vx,vy) = (z1, z2) for output column j
                    float z = vx + bias[j];
                    float g = vy + bias2[j];
                    float h = (z / (1.0f + __expf(-z))) * g;
                    outb[(size_t)m * Nh + j] = __float2bfloat16(h);
                } else if (n < N1) {
                    vx += bias[n]; vy += bias[n + 1];
                    if (residual) {
                        float2 rr = *(const float2*)(residual + (size_t)m * N1 + n);
                        vx = rr.x + gain[n]     * vx;
                        vy = rr.y + gain[n + 1] * vy;
                    }
                    if (outb) {
                        *(__nv_bfloat162*)(outb + (size_t)m * N1 + n) = __floats2bfloat162_rn(vx, vy);
                    } else {
                        *(float2*)(outp + (size_t)m * N1 + n) = make_float2(vx, vy);
                    }
                } else {
                    int S2 = N - N1, n2 = n - N1;
                    vx += bias2[n2]; vy += bias2[n2 + 1];
                    *(float2*)(outp2 + (size_t)m * S2 + n2) = make_float2(vx, vy);
                }
            }
        }
    }
}

// ---------------- deformable-attention sampling ----------------
// 2 tokens/block; warp handles (token, head-pair); 16 lanes/head, bf16x2 channels.
__global__ void __launch_bounds__(256) msda_kernel(
    const float* __restrict__ ref,
    const __nv_bfloat16* __restrict__ value,
    const float* __restrict__ off,
    const float* __restrict__ awl,
    __nv_bfloat16* __restrict__ outp)
{
    int tid   = threadIdx.x;
    int wid   = tid >> 5, lane = tid & 31;
    int token = blockIdx.x * 2 + (wid >> 2);
    int h     = ((wid & 3) << 1) + (lane >> 4);
    int ch2   = lane & 15;

    const float* aw = awl + (size_t)token * 128 + h * 16;
    const float* of = off + (size_t)token * 256 + h * 32;

    float wgt[16];
    float mx = -1e30f;
    #pragma unroll
    for (int s = 0; s < 16; s++) { wgt[s] = aw[s]; mx = fmaxf(mx, wgt[s]); }
    float sum = 0.f;
    #pragma unroll
    for (int s = 0; s < 16; s++) { wgt[s] = __expf(wgt[s] - mx); sum += wgt[s]; }
    float inv = 1.0f / sum;

    int b = token / LQ;
    const __nv_bfloat162* vb = (const __nv_bfloat162*)value + (size_t)b * LQ * 128 + h * 16 + ch2;

    float ax = 0.f, ay = 0.f;
    #pragma unroll
    for (int l = 0; l < 4; l++) {
        const int H  = c_H[l];
        const int W  = c_W[l];
        const int st = c_st[l];
        float rx = ref[(size_t)token * 8 + l * 2 + 0];
        float ry = ref[(size_t)token * 8 + l * 2 + 1];
        #pragma unroll
        for (int p = 0; p < 4; p++) {
            int s = l * 4 + p;
            float x = fmaf(rx, (float)W, of[s * 2 + 0] - 0.5f);
            float y = fmaf(ry, (float)H, of[s * 2 + 1] - 0.5f);
            float x0f = floorf(x), y0f = floorf(y);
            int   x0  = (int)x0f,  y0  = (int)y0f;
            float lx = x - x0f, ly = y - y0f;
            float ws  = wgt[s] * inv;
            float w00 = (1.f - lx) * (1.f - ly) * ws;
            float w01 = lx * (1.f - ly) * ws;
            float w10 = (1.f - lx) * ly * ws;
            float w11 = lx * ly * ws;
            bool x0v = (x0 >= 0)     && (x0 < W);
            bool x1v = (x0 + 1 >= 0) && (x0 + 1 < W);
            if (y0 >= 0 && y0 < H) {
                long long base = (long long)(st + y0 * W) * 128;
                if (x0v) { float2 f = __bfloat1622float2(vb[base + (long long)x0 * 128]);
                           ax += w00 * f.x; ay += w00 * f.y; }
                if (x1v) { float2 f = __bfloat1622float2(vb[base + (long long)(x0 + 1) * 128]);
                           ax += w01 * f.x; ay += w01 * f.y; }
            }
            int y1 = y0 + 1;
            if (y1 >= 0 && y1 < H) {
                long long base = (long long)(st + y1 * W) * 128;
                if (x0v) { float2 f = __bfloat1622float2(vb[base + (long long)x0 * 128]);
                           ax += w10 * f.x; ay += w10 * f.y; }
                if (x1v) { float2 f = __bfloat1622float2(vb[base + (long long)(x0 + 1) * 128]);
                           ax += w11 * f.x; ay += w11 * f.y; }
            }
        }
    }
    *(__nv_bfloat162*)(outp + (size_t)token * 256 + h * 32 + ch2 * 2) = __floats2bfloat162_rn(ax, ay);
}

// ---------------- host launch ----------------
template <typename T>
static T* symaddr(const void* sym) {
    void* p = nullptr;
    cudaGetSymbolAddress(&p, sym);
    return (T*)p;
}

extern "C" void kernel_launch(void* const* d_in, const int* in_sizes, int n_in,
                              void* d_out, int out_size) {
    (void)in_sizes; (void)n_in; (void)out_size;
    const float* query = (const float*)d_in[0];
    const float* qpos  = (const float*)d_in[1];
    const float* ref   = (const float*)d_in[2];
    const float* nw1   = (const float*)d_in[5];
    const float* Wv    = (const float*)d_in[6];
    const float* bv    = (const float*)d_in[7];
    const float* Woff  = (const float*)d_in[8];
    const float* boff  = (const float*)d_in[9];
    const float* Waw   = (const float*)d_in[10];
    const float* baw   = (const float*)d_in[11];
    const float* Wo    = (const float*)d_in[12];
    const float* bo    = (const float*)d_in[13];
    const float* lsa   = (const float*)d_in[14];
    const float* nw2   = (const float*)d_in[15];
    const float* W1    = (const float*)d_in[16];
    const float* b1    = (const float*)d_in[17];
    const float* W2    = (const float*)d_in[18];
    const float* b2    = (const float*)d_in[19];
    const float* W3    = (const float*)d_in[20];
    const float* b3    = (const float*)d_in[21];
    const float* lsf   = (const float*)d_in[22];
    float* out = (float*)d_out;

    __nv_bfloat16* nb    = symaddr<__nv_bfloat16>(g_nb);
    __nv_bfloat16* qb    = symaddr<__nv_bfloat16>(g_qb);
    __nv_bfloat16* valb  = symaddr<__nv_bfloat16>(g_valueb);
    float*         poff  = symaddr<float>(g_off);
    float*         pawl  = symaddr<float>(g_awl);
    __nv_bfloat16* attnb = symaddr<__nv_bfloat16>(g_attnb);
    float*         px    = symaddr<float>(g_x);
    __nv_bfloat16* n2b   = symaddr<__nv_bfloat16>(g_n2b);
    __nv_bfloat16* hb    = symaddr<__nv_bfloat16>(g_hb);
    __nv_bfloat16* wb    = symaddr<__nv_bfloat16>(g_wb);

    const int GSM = NSTAGE * STAGE_BYTES;   // 110592
    cudaFuncSetAttribute(hmma_gemm_kernel, cudaFuncAttributeMaxDynamicSharedMemorySize, GSM);

    // 0. weights -> bf16 (W1/W2 interleaved)
    WSrc ws; ws.s[0] = Wv; ws.s[1] = Woff; ws.s[2] = Waw; ws.s[3] = Wo;
    ws.s[4] = W1; ws.s[5] = W2; ws.s[6] = W3;
    wconv_kernel<<<dim3(256, 7), 256>>>(ws);

    // 1. rmsnorm -> normed bf16, q = normed+pos bf16
    rmsnorm_kernel<<<(MTOK + 7) / 8, 256>>>(query, nw1, nb, qpos, qb);
    // 2. value = normed @ Wv^T + bv  (bf16 out)
    hmma_gemm_kernel<<<dim3(2, MT128), 256, GSM>>>(nb, wb + WOFF_WV, bv, nullptr,
        nullptr, nullptr, valb, MTOK, 256, 256, 256, 0, nullptr, nullptr);
    // 3. fused offsets+logits: q @ [Woff;Waw]^T, split outputs
    hmma_gemm_kernel<<<dim3(3, MT128), 256, GSM>>>(qb, wb + WOFF_WOFF, boff, baw,
        poff, pawl, nullptr, MTOK, 384, 256, 256, 0, nullptr, nullptr);
    // 4. deformable sampling -> attn bf16
    msda_kernel<<<MTOK / 2, 256>>>(ref, valb, poff, pawl, attnb);
    // 5. x = query + ls_attn * (attn @ Wo^T + bo)
    hmma_gemm_kernel<<<dim3(2, MT128), 256, GSM>>>(attnb, wb + WOFF_WO, bo, nullptr,
        px, nullptr, nullptr, MTOK, 256, 256, 256, 0, query, lsa);
    // 6. n2 = rmsnorm(x) bf16
    rmsnorm_kernel<<<(MTOK + 7) / 8, 256>>>(px, nw2, n2b, nullptr, nullptr);
    // 7. FFN-up (interleaved W1/W2, swiglu epilogue) -> h bf16
    hmma_gemm_kernel<<<dim3(16, MT128), 256, GSM>>>(n2b, wb + WOFF_FF, b1, b2,
        nullptr, nullptr, hb, MTOK, 2048, 2048, 256, 1, nullptr, nullptr);
    // 8. out = x + ls_ffn * (h @ W3^T + b3)
    hmma_gemm_kernel<<<dim3(2, MT128), 256, GSM>>>(hb, wb + WOFF_W3, b3, nullptr,
        out, nullptr, nullptr, MTOK, 256, 256, 1024, 0, px, lsf);
}

// round 8
// speedup vs baseline: 1.3413x; 1.2234x over previous
#include <cuda_runtime.h>
#include <cuda_bf16.h>
#include <cstdint>
#include <math.h>

// ---------------- problem constants ----------------
#define BSZ   2
#define LQ    17821
#define CDIM  256
#define MTOK  (BSZ*LQ)          // 35642
#define MPAD  35712             // 279 * 128
#define MT128 279
#define DFFN  1024
#define PAD   72                // smem row stride in halves (144B, conflict-free)

__device__ __constant__ int c_H[4]  = {100, 50, 25, 13};
__device__ __constant__ int c_W[4]  = {134, 67, 34, 17};
__device__ __constant__ int c_st[4] = {0, 13400, 16750, 17600};

// ---------------- scratch (no allocs; zero-initialized .bss) ----------------
__device__ __nv_bfloat16 g_nb    [(size_t)MPAD*CDIM];
__device__ __nv_bfloat16 g_qb    [(size_t)MPAD*CDIM];
__device__ __nv_bfloat16 g_valueb[(size_t)MPAD*CDIM];
__device__ float         g_off   [(size_t)MTOK*CDIM];
__device__ float         g_awl   [(size_t)MTOK*128];
__device__ __nv_bfloat16 g_attnb [(size_t)MPAD*CDIM];
__device__ float         g_x     [(size_t)MTOK*CDIM];
__device__ __nv_bfloat16 g_n2b   [(size_t)MPAD*CDIM];
__device__ __nv_bfloat16 g_hb    [(size_t)MPAD*DFFN];
// converted weights: Wv,Woff,Waw,Wo,W1,W2,W3
#define WOFF_WV   0
#define WOFF_WOFF 65536
#define WOFF_WAW  131072
#define WOFF_WO   163840
#define WOFF_W1   229376
#define WOFF_W2   491520
#define WOFF_W3   753664
__device__ __nv_bfloat16 g_wb[1015808];

// ================= helpers =================
__device__ __forceinline__ uint32_t smem_u32(const void* p) {
    uint32_t a;
    asm("{ .reg .u64 t; cvta.to.shared.u64 t, %1; cvt.u32.u64 %0, t; }" : "=r"(a) : "l"(p));
    return a;
}
__device__ __forceinline__ void ldsm4(uint32_t* r, uint32_t addr) {
    asm volatile("ldmatrix.sync.aligned.m8n8.x4.shared.b16 {%0,%1,%2,%3}, [%4];"
        : "=r"(r[0]), "=r"(r[1]), "=r"(r[2]), "=r"(r[3]) : "r"(addr));
}
__device__ __forceinline__ void mma_bf16(float* c, const uint32_t* a, const uint32_t* b) {
    asm volatile(
        "mma.sync.aligned.m16n8k16.row.col.f32.bf16.bf16.f32 "
        "{%0,%1,%2,%3}, {%4,%5,%6,%7}, {%8,%9}, {%0,%1,%2,%3};"
        : "+f"(c[0]), "+f"(c[1]), "+f"(c[2]), "+f"(c[3])
        : "r"(a[0]), "r"(a[1]), "r"(a[2]), "r"(a[3]), "r"(b[0]), "r"(b[1]));
}
__device__ __forceinline__ void cp16(uint32_t dst, const void* src) {
    asm volatile("cp.async.ca.shared.global [%0], [%1], 16;" :: "r"(dst), "l"(src));
}
#define CP_COMMIT() asm volatile("cp.async.commit_group;" ::: "memory")
#define CP_WAIT1()  asm volatile("cp.async.wait_group 1;" ::: "memory")
#define CP_WAIT0()  asm volatile("cp.async.wait_group 0;" ::: "memory")

// ---------------- weight fp32 -> bf16 convert ----------------
struct WSrc { const float* s[7]; };
__device__ __constant__ int c_wsz [7] = {65536, 65536, 32768, 65536, 262144, 262144, 262144};
__device__ __constant__ int c_woff[7] = {WOFF_WV, WOFF_WOFF, WOFF_WAW, WOFF_WO, WOFF_W1, WOFF_W2, WOFF_W3};

__global__ void __launch_bounds__(256) wconv_kernel(WSrc w) {
    int seg = blockIdx.y;
    int i = (blockIdx.x * 256 + threadIdx.x) * 4;
    if (i >= c_wsz[seg]) return;
    float4 v = *(const float4*)(w.s[seg] + i);
    __nv_bfloat16* d = g_wb + c_woff[seg] + i;
    *(__nv_bfloat162*)(d)     = __floats2bfloat162_rn(v.x, v.y);
    *(__nv_bfloat162*)(d + 2) = __floats2bfloat162_rn(v.z, v.w);
}

// ---------------- RMSNorm -> bf16 (+ optional bf16 normed+addend) ----------------
__global__ void __launch_bounds__(256) rmsnorm_kernel(
    const float* __restrict__ x, const float* __restrict__ w,
    __nv_bfloat16* __restrict__ out, const float* __restrict__ addend,
    __nv_bfloat16* __restrict__ out2)
{
    int row  = blockIdx.x * 8 + (threadIdx.x >> 5);
    if (row >= MTOK) return;
    int lane = threadIdx.x & 31;
    const float4* xr = (const float4*)(x + (size_t)row * CDIM);
    float4 v0 = xr[lane];
    float4 v1 = xr[lane + 32];
    float ss = v0.x*v0.x + v0.y*v0.y + v0.z*v0.z + v0.w*v0.w
             + v1.x*v1.x + v1.y*v1.y + v1.z*v1.z + v1.w*v1.w;
    #pragma unroll
    for (int o = 16; o > 0; o >>= 1) ss += __shfl_xor_sync(0xffffffffu, ss, o);
    float s = rsqrtf(ss * (1.0f / CDIM) + 1e-6f);
    const float4* w4 = (const float4*)w;
    float4 g0 = w4[lane], g1 = w4[lane + 32];
    float n0x = v0.x*s*g0.x, n0y = v0.y*s*g0.y, n0z = v0.z*s*g0.z, n0w = v0.w*s*g0.w;
    float n1x = v1.x*s*g1.x, n1y = v1.y*s*g1.y, n1z = v1.z*s*g1.z, n1w = v1.w*s*g1.w;
    __nv_bfloat162* o2 = (__nv_bfloat162*)(out + (size_t)row * CDIM);
    o2[lane*2+0]  = __floats2bfloat162_rn(n0x, n0y);
    o2[lane*2+1]  = __floats2bfloat162_rn(n0z, n0w);
    o2[64+lane*2] = __floats2bfloat162_rn(n1x, n1y);
    o2[65+lane*2] = __floats2bfloat162_rn(n1z, n1w);
    if (out2) {
        const float4* a4 = (const float4*)(addend + (size_t)row * CDIM);
        float4 p0 = a4[lane], p1 = a4[lane + 32];
        __nv_bfloat162* q2 = (__nv_bfloat162*)(out2 + (size_t)row * CDIM);
        q2[lane*2+0]  = __floats2bfloat162_rn(n0x + p0.x, n0y + p0.y);
        q2[lane*2+1]  = __floats2bfloat162_rn(n0z + p0.z, n0w + p0.w);
        q2[64+lane*2] = __floats2bfloat162_rn(n1x + p1.x, n1y + p1.y);
        q2[65+lane*2] = __floats2bfloat162_rn(n1z + p1.z, n1w + p1.w);
    }
}

// ---------------- HMMA GEMM, 3-stage cp.async ring (R5 config) ----------------
// out[m,n] = sum_k A[m,k]*B[n,k] + bias[n], n in [0,N1); split tail to outp2.
// optional residual+gain epilogue (N1==N only); optional bf16 out.
// CTA tile 128x128, 8 warps (each 64x32), K chunk 64.
#define TILE_BYTES  (128 * PAD * 2)     // 18432
#define STAGE_BYTES (2 * TILE_BYTES)    // 36864: [As | Bs]
#define NSTAGE 3

__global__ void __launch_bounds__(256) hmma_gemm_kernel(
    const __nv_bfloat16* __restrict__ A, const __nv_bfloat16* __restrict__ B,
    const float* __restrict__ bias, const float* __restrict__ bias2,
    float* __restrict__ outp, float* __restrict__ outp2,
    __nv_bfloat16* __restrict__ outb,
    int M, int N, int N1, int K,
    const float* __restrict__ residual, const float* __restrict__ gain)
{
    extern __shared__ __align__(16) char smem[];
    uint32_t sb = smem_u32(smem);
    int tid = threadIdx.x, lane = tid & 31, wid = tid >> 5;
    int m0 = blockIdx.y * 128, n0 = blockIdx.x * 128;
    int warp_m = (wid & 1) * 64, warp_n = (wid >> 1) * 32;

    float acc[4][4][4] = {};

    int sub = lane >> 3, lrow = lane & 7;
    uint32_t a_off = ((warp_m + (sub & 1) * 8 + lrow) * PAD + (sub >> 1) * 8) * 2;
    uint32_t b_off = TILE_BYTES + ((warp_n + (sub >> 1) * 8 + lrow) * PAD + (sub & 1) * 8) * 2;

    const int NCH = K >> 6;
    const int ld4 = K >> 3;
    int lrow4 = tid >> 3, lcol4 = tid & 7;
    const uint4* agl = (const uint4*)(A + (size_t)m0 * K) + (size_t)lrow4 * ld4 + lcol4;
    const uint4* bgl = (const uint4*)(B + (size_t)n0 * K) + (size_t)lrow4 * ld4 + lcol4;
    uint32_t sdst = sb + lrow4 * (PAD * 2) + lcol4 * 16;

    #pragma unroll
    for (int s = 0; s < 2; s++) {
        if (s < NCH) {
            uint32_t d = sdst + s * STAGE_BYTES;
            const uint4* ag = agl + (size_t)s * 8;
            const uint4* bg = bgl + (size_t)s * 8;
            #pragma unroll
            for (int p = 0; p < 4; p++) {
                cp16(d + p * 32 * (PAD * 2),              ag + (size_t)p * 32 * ld4);
                cp16(d + TILE_BYTES + p * 32 * (PAD * 2), bg + (size_t)p * 32 * ld4);
            }
        }
        CP_COMMIT();
    }

    int stage = 0, lstage = 2;
    for (int c = 0; c < NCH; c++) {
        if (c + 1 < NCH) CP_WAIT1(); else CP_WAIT0();
        __syncthreads();
        if (c + 2 < NCH) {
            uint32_t d = sdst + lstage * STAGE_BYTES;
            const uint4* ag = agl + (size_t)(c + 2) * 8;
            const uint4* bg = bgl + (size_t)(c + 2) * 8;
            #pragma unroll
            for (int p = 0; p < 4; p++) {
                cp16(d + p * 32 * (PAD * 2),              ag + (size_t)p * 32 * ld4);
                cp16(d + TILE_BYTES + p * 32 * (PAD * 2), bg + (size_t)p * 32 * ld4);
            }
            CP_COMMIT();
            if (++lstage == NSTAGE) lstage = 0;
        }
        uint32_t ab = sb + stage * STAGE_BYTES + a_off;
        uint32_t bb = sb + stage * STAGE_BYTES + b_off;
        #pragma unroll
        for (int ks = 0; ks < 4; ks++) {
            uint32_t af[4][4], bf[2][4];
            #pragma unroll
            for (int mt = 0; mt < 4; mt++) ldsm4(af[mt], ab + (mt * 16 * PAD + ks * 16) * 2);
            #pragma unroll
            for (int pr = 0; pr < 2; pr++) ldsm4(bf[pr], bb + (pr * 16 * PAD + ks * 16) * 2);
            #pragma unroll
            for (int mt = 0; mt < 4; mt++) {
                mma_bf16(acc[mt][0], af[mt], &bf[0][0]);
                mma_bf16(acc[mt][1], af[mt], &bf[0][2]);
                mma_bf16(acc[mt][2], af[mt], &bf[1][0]);
                mma_bf16(acc[mt][3], af[mt], &bf[1][2]);
            }
        }
        if (++stage == NSTAGE) stage = 0;
    }

    int crow = lane >> 2, ccol = (lane & 3) * 2;
    #pragma unroll
    for (int mt = 0; mt < 4; mt++) {
        #pragma unroll
        for (int half = 0; half < 2; half++) {
            int m = m0 + warp_m + mt * 16 + crow + half * 8;
            if (m >= M) continue;
            #pragma unroll
            for (int nt = 0; nt < 4; nt++) {
                int n = n0 + warp_n + nt * 8 + ccol;
                if (n < N1) {
                    float vx = acc[mt][nt][half * 2 + 0] + bias[n];
                    float vy = acc[mt][nt][half * 2 + 1] + bias[n + 1];
                    if (residual) {
                        float2 rr = *(const float2*)(residual + (size_t)m * N1 + n);
                        vx = rr.x + gain[n]     * vx;
                        vy = rr.y + gain[n + 1] * vy;
                    }
                    if (outb) {
                        *(__nv_bfloat162*)(outb + (size_t)m * N1 + n) = __floats2bfloat162_rn(vx, vy);
                    } else {
                        *(float2*)(outp + (size_t)m * N1 + n) = make_float2(vx, vy);
                    }
                } else {
                    int S2 = N - N1, n2 = n - N1;
                    float vx = acc[mt][nt][half * 2 + 0] + bias2[n2];
                    float vy = acc[mt][nt][half * 2 + 1] + bias2[n2 + 1];
                    *(float2*)(outp2 + (size_t)m * S2 + n2) = make_float2(vx, vy);
                }
            }
        }
    }
}

// ---------------- fused FFN-up, 3-stage cp.async ring (R5 config) ----------------
#define DTILE_A  (128 * PAD * 2)                    // 18432
#define DTILE_B  (64 * PAD * 2)                     // 9216
#define DSTAGE   (DTILE_A + 2 * DTILE_B)            // 36864

__global__ void __launch_bounds__(256) hmma_dual_kernel(
    const __nv_bfloat16* __restrict__ A,
    const __nv_bfloat16* __restrict__ B1, const float* __restrict__ b1,
    const __nv_bfloat16* __restrict__ B2, const float* __restrict__ b2,
    __nv_bfloat16* __restrict__ outp, int M, int N, int K)
{
    extern __shared__ __align__(16) char smem[];
    uint32_t sb = smem_u32(smem);
    int tid = threadIdx.x, lane = tid & 31, wid = tid >> 5;
    int m0 = blockIdx.y * 128, n0 = blockIdx.x * 64;
    int warp_m = (wid & 1) * 64, warp_n = (wid >> 1) * 16;

    float acc1[4][2][4] = {}, acc2[4][2][4] = {};

    int sub = lane >> 3, lrow = lane & 7;
    uint32_t a_off  = ((warp_m + (sub & 1) * 8 + lrow) * PAD + (sub >> 1) * 8) * 2;
    uint32_t b1_off = DTILE_A + ((warp_n + (sub >> 1) * 8 + lrow) * PAD + (sub & 1) * 8) * 2;
    uint32_t b2_off = DTILE_A + DTILE_B + ((warp_n + (sub >> 1) * 8 + lrow) * PAD + (sub & 1) * 8) * 2;

    const int NCH = K >> 6;
    const int ld4 = K >> 3;
    int lrow4 = tid >> 3, lcol4 = tid & 7;
    const uint4* agl  = (const uint4*)(A  + (size_t)m0 * K) + (size_t)lrow4 * ld4 + lcol4;
    const uint4* bgl1 = (const uint4*)(B1 + (size_t)n0 * K) + (size_t)lrow4 * ld4 + lcol4;
    const uint4* bgl2 = (const uint4*)(B2 + (size_t)n0 * K) + (size_t)lrow4 * ld4 + lcol4;
    uint32_t sdst = sb + lrow4 * (PAD * 2) + lcol4 * 16;
    bool bload = (lrow4 < 64);

    #pragma unroll
    for (int s = 0; s < 2; s++) {
        if (s < NCH) {
            uint32_t d = sdst + s * DSTAGE;
            const uint4* ag = agl + (size_t)s * 8;
            #pragma unroll
            for (int p = 0; p < 4; p++)
                cp16(d + p * 32 * (PAD * 2), ag + (size_t)p * 32 * ld4);
            if (bload) {
                const uint4* bg1 = bgl1 + (size_t)s * 8;
                const uint4* bg2 = bgl2 + (size_t)s * 8;
                cp16(d + DTILE_A,              bg1);
                cp16(d + DTILE_A + 32*(PAD*2), bg1 + (size_t)32 * ld4);
                cp16(d + DTILE_A + DTILE_B,              bg2);
                cp16(d + DTILE_A + DTILE_B + 32*(PAD*2), bg2 + (size_t)32 * ld4);
            }
        }
        CP_COMMIT();
    }

    int stage = 0, lstage = 2;
    for (int c = 0; c < NCH; c++) {
        if (c + 1 < NCH) CP_WAIT1(); else CP_WAIT0();
        __syncthreads();
        if (c + 2 < NCH) {
            uint32_t d = sdst + lstage * DSTAGE;
            const uint4* ag = agl + (size_t)(c + 2) * 8;
            #pragma unroll
            for (int p = 0; p < 4; p++)
                cp16(d + p * 32 * (PAD * 2), ag + (size_t)p * 32 * ld4);
            if (bload) {
                const uint4* bg1 = bgl1 + (size_t)(c + 2) * 8;
                const uint4* bg2 = bgl2 + (size_t)(c + 2) * 8;
                cp16(d + DTILE_A,              bg1);
                cp16(d + DTILE_A + 32*(PAD*2), bg1 + (size_t)32 * ld4);
                cp16(d + DTILE_A + DTILE_B,              bg2);
                cp16(d + DTILE_A + DTILE_B + 32*(PAD*2), bg2 + (size_t)32 * ld4);
            }
            CP_COMMIT();
            if (++lstage == NSTAGE) lstage = 0;
        }
        uint32_t ab  = sb + stage * DSTAGE + a_off;
        uint32_t bb1 = sb + stage * DSTAGE + b1_off;
        uint32_t bb2 = sb + stage * DSTAGE + b2_off;
        #pragma unroll
        for (int ks = 0; ks < 4; ks++) {
            uint32_t af[4][4], bf1[4], bf2[4];
            #pragma unroll
            for (int mt = 0; mt < 4; mt++) ldsm4(af[mt], ab + (mt * 16 * PAD + ks * 16) * 2);
            ldsm4(bf1, bb1 + (ks * 16) * 2);
            ldsm4(bf2, bb2 + (ks * 16) * 2);
            #pragma unroll
            for (int mt = 0; mt < 4; mt++) {
                mma_bf16(acc1[mt][0], af[mt], &bf1[0]);
                mma_bf16(acc1[mt][1], af[mt], &bf1[2]);
                mma_bf16(acc2[mt][0], af[mt], &bf2[0]);
                mma_bf16(acc2[mt][1], af[mt], &bf2[2]);
            }
        }
        if (++stage == NSTAGE) stage = 0;
    }

    int crow = lane >> 2, ccol = (lane & 3) * 2;
    #pragma unroll
    for (int mt = 0; mt < 4; mt++) {
        #pragma unroll
        for (int half = 0; half < 2; half++) {
            int m = m0 + warp_m + mt * 16 + crow + half * 8;
            if (m >= M) continue;
            #pragma unroll
            for (int nt = 0; nt < 2; nt++) {
                int n = n0 + warp_n + nt * 8 + ccol;
                float z0 = acc1[mt][nt][half * 2 + 0] + b1[n];
                float z1 = acc1[mt][nt][half * 2 + 1] + b1[n + 1];
                float g0 = acc2[mt][nt][half * 2 + 0] + b2[n];
                float g1 = acc2[mt][nt][half * 2 + 1] + b2[n + 1];
                float h0 = (z0 / (1.0f + __expf(-z0))) * g0;
                float h1 = (z1 / (1.0f + __expf(-z1))) * g1;
                *(__nv_bfloat162*)(outp + (size_t)m * N + n) = __floats2bfloat162_rn(h0, h1);
            }
        }
    }
}

// ---------------- deformable-attention sampling ----------------
// 4 tokens/block; warp = 4 heads x 8 lanes; each lane handles 4 channels (uint2 of bf16x4).
__global__ void __launch_bounds__(256) msda_kernel(
    const float* __restrict__ ref,
    const __nv_bfloat16* __restrict__ value,
    const float* __restrict__ off,
    const float* __restrict__ awl,
    __nv_bfloat16* __restrict__ outp)
{
    int tid   = threadIdx.x;
    int wid   = tid >> 5, lane = tid & 31;
    int token = blockIdx.x * 4 + (wid >> 1);
    if (token >= MTOK) return;
    int h  = ((wid & 1) << 2) + (lane >> 3);
    int cg = lane & 7;                         // uint2 group (4 bf16 channels)

    const float* aw = awl + (size_t)token * 128 + h * 16;
    const float* of = off + (size_t)token * 256 + h * 32;

    float wgt[16];
    float mx = -1e30f;
    #pragma unroll
    for (int s = 0; s < 16; s++) { wgt[s] = aw[s]; mx = fmaxf(mx, wgt[s]); }
    float sum = 0.f;
    #pragma unroll
    for (int s = 0; s < 16; s++) { wgt[s] = __expf(wgt[s] - mx); sum += wgt[s]; }
    float inv = 1.0f / sum;

    int b = token / LQ;
    const uint2* vb = (const uint2*)value + (size_t)b * LQ * 64 + h * 8 + cg;

    float ax0 = 0.f, ay0 = 0.f, ax1 = 0.f, ay1 = 0.f;
    #pragma unroll
    for (int l = 0; l < 4; l++) {
        const int H  = c_H[l];
        const int W  = c_W[l];
        const int st = c_st[l];
        float rx = ref[(size_t)token * 8 + l * 2 + 0];
        float ry = ref[(size_t)token * 8 + l * 2 + 1];
        #pragma unroll
        for (int p = 0; p < 4; p++) {
            int s = l * 4 + p;
            float x = fmaf(rx, (float)W, of[s * 2 + 0] - 0.5f);
            float y = fmaf(ry, (float)H, of[s * 2 + 1] - 0.5f);
            float x0f = floorf(x), y0f = floorf(y);
            int   x0  = (int)x0f,  y0  = (int)y0f;
            float lx = x - x0f, ly = y - y0f;
            float ws  = wgt[s] * inv;
            float w00 = (1.f - lx) * (1.f - ly) * ws;
            float w01 = lx * (1.f - ly) * ws;
            float w10 = (1.f - lx) * ly * ws;
            float w11 = lx * ly * ws;
            bool x0v = (x0 >= 0)     && (x0 < W);
            bool x1v = (x0 + 1 >= 0) && (x0 + 1 < W);
            #pragma unroll
            for (int dy = 0; dy < 2; dy++) {
                int yy = y0 + dy;
                if (yy < 0 || yy >= H) continue;
                long long base = (long long)(st + yy * W) * 64;
                float wa = dy ? w10 : w00;
                float wb2 = dy ? w11 : w01;
                if (x0v) {
                    uint2 v = vb[base + (long long)x0 * 64];
                    float2 f0 = __bfloat1622float2(*(__nv_bfloat162*)&v.x);
                    float2 f1 = __bfloat1622float2(*(__nv_bfloat162*)&v.y);
                    ax0 += wa * f0.x; ay0 += wa * f0.y;
                    ax1 += wa * f1.x; ay1 += wa * f1.y;
                }
                if (x1v) {
                    uint2 v = vb[base + (long long)(x0 + 1) * 64];
                    float2 f0 = __bfloat1622float2(*(__nv_bfloat162*)&v.x);
                    float2 f1 = __bfloat1622float2(*(__nv_bfloat162*)&v.y);
                    ax0 += wb2 * f0.x; ay0 += wb2 * f0.y;
                    ax1 += wb2 * f1.x; ay1 += wb2 * f1.y;
                }
            }
        }
    }
    uint2 o;
    *(__nv_bfloat162*)&o.x = __floats2bfloat162_rn(ax0, ay0);
    *(__nv_bfloat162*)&o.y = __floats2bfloat162_rn(ax1, ay1);
    *(uint2*)(outp + (size_t)token * 256 + h * 32 + cg * 4) = o;
}

// ---------------- host launch ----------------
template <typename T>
static T* symaddr(const void* sym) {
    void* p = nullptr;
    cudaGetSymbolAddress(&p, sym);
    return (T*)p;
}

extern "C" void kernel_launch(void* const* d_in, const int* in_sizes, int n_in,
                              void* d_out, int out_size) {
    (void)in_sizes; (void)n_in; (void)out_size;
    const float* query = (const float*)d_in[0];
    const float* qpos  = (const float*)d_in[1];
    const float* ref   = (const float*)d_in[2];
    const float* nw1   = (const float*)d_in[5];
    const float* Wv    = (const float*)d_in[6];
    const float* bv    = (const float*)d_in[7];
    const float* Woff  = (const float*)d_in[8];
    const float* boff  = (const float*)d_in[9];
    const float* Waw   = (const float*)d_in[10];
    const float* baw   = (const float*)d_in[11];
    const float* Wo    = (const float*)d_in[12];
    const float* bo    = (const float*)d_in[13];
    const float* lsa   = (const float*)d_in[14];
    const float* nw2   = (const float*)d_in[15];
    const float* W1    = (const float*)d_in[16];
    const float* b1    = (const float*)d_in[17];
    const float* W2    = (const float*)d_in[18];
    const float* b2    = (const float*)d_in[19];
    const float* W3    = (const float*)d_in[20];
    const float* b3    = (const float*)d_in[21];
    const float* lsf   = (const float*)d_in[22];
    float* out = (float*)d_out;

    __nv_bfloat16* nb    = symaddr<__nv_bfloat16>(g_nb);
    __nv_bfloat16* qb    = symaddr<__nv_bfloat16>(g_qb);
    __nv_bfloat16* valb  = symaddr<__nv_bfloat16>(g_valueb);
    float*         poff  = symaddr<float>(g_off);
    float*         pawl  = symaddr<float>(g_awl);
    __nv_bfloat16* attnb = symaddr<__nv_bfloat16>(g_attnb);
    float*         px    = symaddr<float>(g_x);
    __nv_bfloat16* n2b   = symaddr<__nv_bfloat16>(g_n2b);
    __nv_bfloat16* hb    = symaddr<__nv_bfloat16>(g_hb);
    __nv_bfloat16* wb    = symaddr<__nv_bfloat16>(g_wb);

    const int GSM = NSTAGE * STAGE_BYTES;   // 110592
    const int DSM = NSTAGE * DSTAGE;        // 110592
    cudaFuncSetAttribute(hmma_gemm_kernel, cudaFuncAttributeMaxDynamicSharedMemorySize, GSM);
    cudaFuncSetAttribute(hmma_dual_kernel, cudaFuncAttributeMaxDynamicSharedMemorySize, DSM);

    // 0. weights -> bf16
    WSrc ws; ws.s[0] = Wv; ws.s[1] = Woff; ws.s[2] = Waw; ws.s[3] = Wo;
    ws.s[4] = W1; ws.s[5] = W2; ws.s[6] = W3;
    wconv_kernel<<<dim3(256, 7), 256>>>(ws);

    // 1. rmsnorm -> normed bf16, q = normed+pos bf16
    rmsnorm_kernel<<<(MTOK + 7) / 8, 256>>>(query, nw1, nb, qpos, qb);
    // 2. value = normed @ Wv^T + bv  (bf16 out)
    hmma_gemm_kernel<<<dim3(2, MT128), 256, GSM>>>(nb, wb + WOFF_WV, bv, nullptr,
        nullptr, nullptr, valb, MTOK, 256, 256, 256, nullptr, nullptr);
    // 3. fused offsets+logits: q @ [Woff;Waw]^T, split outputs
    hmma_gemm_kernel<<<dim3(3, MT128), 256, GSM>>>(qb, wb + WOFF_WOFF, boff, baw,
        poff, pawl, nullptr, MTOK, 384, 256, 256, nullptr, nullptr);
    // 4. deformable sampling -> attn bf16 (4 tokens/block)
    msda_kernel<<<(MTOK + 3) / 4, 256>>>(ref, valb, poff, pawl, attnb);
    // 5. x = query + ls_attn * (attn @ Wo^T + bo)
    hmma_gemm_kernel<<<dim3(2, MT128), 256, GSM>>>(attnb, wb + WOFF_WO, bo, nullptr,
        px, nullptr, nullptr, MTOK, 256, 256, 256, query, lsa);
    // 6. n2 = rmsnorm(x) bf16
    rmsnorm_kernel<<<(MTOK + 7) / 8, 256>>>(px, nw2, n2b, nullptr, nullptr);
    // 7. h = silu(n2@W1^T+b1)*(n2@W2^T+b2) bf16
    hmma_dual_kernel<<<dim3(16, MT128), 256, DSM>>>(n2b, wb + WOFF_W1, b1, wb + WOFF_W2, b2, hb, MTOK, DFFN, 256);
    // 8. out = x + ls_ffn * (h @ W3^T + b3)
    hmma_gemm_kernel<<<dim3(2, MT128), 256, GSM>>>(hb, wb + WOFF_W3, b3, nullptr,
        out, nullptr, nullptr, MTOK, 256, 256, 1024, px, lsf);
}

// round 9
// speedup vs baseline: 1.4612x; 1.0894x over previous
#include <cuda_runtime.h>
#include <cuda_bf16.h>
#include <cuda_fp16.h>
#include <cstdint>
#include <math.h>

// ---------------- problem constants ----------------
#define BSZ   2
#define LQ    17821
#define CDIM  256
#define MTOK  (BSZ*LQ)          // 35642
#define MPAD  35712             // 279 * 128
#define MT128 279
#define DFFN  1024
#define PAD   72                // smem row stride in halves (144B, conflict-free)

__device__ __constant__ int c_H[4]  = {100, 50, 25, 13};
__device__ __constant__ int c_W[4]  = {134, 67, 34, 17};
__device__ __constant__ int c_st[4] = {0, 13400, 16750, 17600};

// ---------------- scratch (no allocs; zero-initialized .bss) ----------------
__device__ __nv_bfloat16 g_nb    [(size_t)MPAD*CDIM];
__device__ __nv_bfloat16 g_qb    [(size_t)MPAD*CDIM];
__device__ __nv_bfloat16 g_valueb[(size_t)MPAD*CDIM];
__device__ __half        g_off   [(size_t)MTOK*CDIM];
__device__ __half        g_awl   [(size_t)MTOK*128];
__device__ __nv_bfloat16 g_attnb [(size_t)MPAD*CDIM];
__device__ float         g_x     [(size_t)MTOK*CDIM];
__device__ __nv_bfloat16 g_n2b   [(size_t)MPAD*CDIM];
__device__ __nv_bfloat16 g_hb    [(size_t)MPAD*DFFN];
// converted weights: Wv,Woff,Waw,Wo,W1,W2,W3
#define WOFF_WV   0
#define WOFF_WOFF 65536
#define WOFF_WAW  131072
#define WOFF_WO   163840
#define WOFF_W1   229376
#define WOFF_W2   491520
#define WOFF_W3   753664
__device__ __nv_bfloat16 g_wb[1015808];

// ================= helpers =================
__device__ __forceinline__ uint32_t smem_u32(const void* p) {
    uint32_t a;
    asm("{ .reg .u64 t; cvta.to.shared.u64 t, %1; cvt.u32.u64 %0, t; }" : "=r"(a) : "l"(p));
    return a;
}
__device__ __forceinline__ void ldsm4(uint32_t* r, uint32_t addr) {
    asm volatile("ldmatrix.sync.aligned.m8n8.x4.shared.b16 {%0,%1,%2,%3}, [%4];"
        : "=r"(r[0]), "=r"(r[1]), "=r"(r[2]), "=r"(r[3]) : "r"(addr));
}
__device__ __forceinline__ void mma_bf16(float* c, const uint32_t* a, const uint32_t* b) {
    asm volatile(
        "mma.sync.aligned.m16n8k16.row.col.f32.bf16.bf16.f32 "
        "{%0,%1,%2,%3}, {%4,%5,%6,%7}, {%8,%9}, {%0,%1,%2,%3};"
        : "+f"(c[0]), "+f"(c[1]), "+f"(c[2]), "+f"(c[3])
        : "r"(a[0]), "r"(a[1]), "r"(a[2]), "r"(a[3]), "r"(b[0]), "r"(b[1]));
}
__device__ __forceinline__ void cp16(uint32_t dst, const void* src) {
    asm volatile("cp.async.ca.shared.global [%0], [%1], 16;" :: "r"(dst), "l"(src));
}
#define CP_COMMIT() asm volatile("cp.async.commit_group;" ::: "memory")
#define CP_WAIT1()  asm volatile("cp.async.wait_group 1;" ::: "memory")
#define CP_WAIT0()  asm volatile("cp.async.wait_group 0;" ::: "memory")

// ---------------- weight fp32 -> bf16 convert ----------------
struct WSrc { const float* s[7]; };
__device__ __constant__ int c_wsz [7] = {65536, 65536, 32768, 65536, 262144, 262144, 262144};
__device__ __constant__ int c_woff[7] = {WOFF_WV, WOFF_WOFF, WOFF_WAW, WOFF_WO, WOFF_W1, WOFF_W2, WOFF_W3};

__global__ void __launch_bounds__(256) wconv_kernel(WSrc w) {
    int seg = blockIdx.y;
    int i = (blockIdx.x * 256 + threadIdx.x) * 4;
    if (i >= c_wsz[seg]) return;
    float4 v = *(const float4*)(w.s[seg] + i);
    __nv_bfloat16* d = g_wb + c_woff[seg] + i;
    *(__nv_bfloat162*)(d)     = __floats2bfloat162_rn(v.x, v.y);
    *(__nv_bfloat162*)(d + 2) = __floats2bfloat162_rn(v.z, v.w);
}

// ---------------- RMSNorm -> bf16 (+ optional bf16 normed+addend) ----------------
__global__ void __launch_bounds__(256) rmsnorm_kernel(
    const float* __restrict__ x, const float* __restrict__ w,
    __nv_bfloat16* __restrict__ out, const float* __restrict__ addend,
    __nv_bfloat16* __restrict__ out2)
{
    int row  = blockIdx.x * 8 + (threadIdx.x >> 5);
    if (row >= MTOK) return;
    int lane = threadIdx.x & 31;
    const float4* xr = (const float4*)(x + (size_t)row * CDIM);
    float4 v0 = xr[lane];
    float4 v1 = xr[lane + 32];
    float ss = v0.x*v0.x + v0.y*v0.y + v0.z*v0.z + v0.w*v0.w
             + v1.x*v1.x + v1.y*v1.y + v1.z*v1.z + v1.w*v1.w;
    #pragma unroll
    for (int o = 16; o > 0; o >>= 1) ss += __shfl_xor_sync(0xffffffffu, ss, o);
    float s = rsqrtf(ss * (1.0f / CDIM) + 1e-6f);
    const float4* w4 = (const float4*)w;
    float4 g0 = w4[lane], g1 = w4[lane + 32];
    float n0x = v0.x*s*g0.x, n0y = v0.y*s*g0.y, n0z = v0.z*s*g0.z, n0w = v0.w*s*g0.w;
    float n1x = v1.x*s*g1.x, n1y = v1.y*s*g1.y, n1z = v1.z*s*g1.z, n1w = v1.w*s*g1.w;
    __nv_bfloat162* o2 = (__nv_bfloat162*)(out + (size_t)row * CDIM);
    o2[lane*2+0]  = __floats2bfloat162_rn(n0x, n0y);
    o2[lane*2+1]  = __floats2bfloat162_rn(n0z, n0w);
    o2[64+lane*2] = __floats2bfloat162_rn(n1x, n1y);
    o2[65+lane*2] = __floats2bfloat162_rn(n1z, n1w);
    if (out2) {
        const float4* a4 = (const float4*)(addend + (size_t)row * CDIM);
        float4 p0 = a4[lane], p1 = a4[lane + 32];
        __nv_bfloat162* q2 = (__nv_bfloat162*)(out2 + (size_t)row * CDIM);
        q2[lane*2+0]  = __floats2bfloat162_rn(n0x + p0.x, n0y + p0.y);
        q2[lane*2+1]  = __floats2bfloat162_rn(n0z + p0.z, n0w + p0.w);
        q2[64+lane*2] = __floats2bfloat162_rn(n1x + p1.x, n1y + p1.y);
        q2[65+lane*2] = __floats2bfloat162_rn(n1z + p1.z, n1w + p1.w);
    }
}

// ---------------- HMMA GEMM, 3-stage cp.async ring ----------------
// out[m,n] = sum_k A[m,k]*B[n,k] + bias[n].
// If outp2 != null: split-half mode — n<N1 -> (half*)outp, n>=N1 -> (half*)outp2.
// Else: fp32 outp (optional residual+gain) or bf16 outb.
// CTA tile 128x128, 8 warps (each 64x32), K chunk 64.
#define TILE_BYTES  (128 * PAD * 2)     // 18432
#define STAGE_BYTES (2 * TILE_BYTES)    // 36864: [As | Bs]
#define NSTAGE 3

__global__ void __launch_bounds__(256) hmma_gemm_kernel(
    const __nv_bfloat16* __restrict__ A, const __nv_bfloat16* __restrict__ B,
    const float* __restrict__ bias, const float* __restrict__ bias2,
    float* __restrict__ outp, float* __restrict__ outp2,
    __nv_bfloat16* __restrict__ outb,
    int M, int N, int N1, int K,
    const float* __restrict__ residual, const float* __restrict__ gain)
{
    extern __shared__ __align__(16) char smem[];
    uint32_t sb = smem_u32(smem);
    int tid = threadIdx.x, lane = tid & 31, wid = tid >> 5;
    int m0 = blockIdx.y * 128, n0 = blockIdx.x * 128;
    int warp_m = (wid & 1) * 64, warp_n = (wid >> 1) * 32;

    float acc[4][4][4] = {};

    int sub = lane >> 3, lrow = lane & 7;
    uint32_t a_off = ((warp_m + (sub & 1) * 8 + lrow) * PAD + (sub >> 1) * 8) * 2;
    uint32_t b_off = TILE_BYTES + ((warp_n + (sub >> 1) * 8 + lrow) * PAD + (sub & 1) * 8) * 2;

    const int NCH = K >> 6;
    const int ld4 = K >> 3;
    int lrow4 = tid >> 3, lcol4 = tid & 7;
    const uint4* agl = (const uint4*)(A + (size_t)m0 * K) + (size_t)lrow4 * ld4 + lcol4;
    const uint4* bgl = (const uint4*)(B + (size_t)n0 * K) + (size_t)lrow4 * ld4 + lcol4;
    uint32_t sdst = sb + lrow4 * (PAD * 2) + lcol4 * 16;

    #pragma unroll
    for (int s = 0; s < 2; s++) {
        if (s < NCH) {
            uint32_t d = sdst + s * STAGE_BYTES;
            const uint4* ag = agl + (size_t)s * 8;
            const uint4* bg = bgl + (size_t)s * 8;
            #pragma unroll
            for (int p = 0; p < 4; p++) {
                cp16(d + p * 32 * (PAD * 2),              ag + (size_t)p * 32 * ld4);
                cp16(d + TILE_BYTES + p * 32 * (PAD * 2), bg + (size_t)p * 32 * ld4);
            }
        }
        CP_COMMIT();
    }

    int stage = 0, lstage = 2;
    for (int c = 0; c < NCH; c++) {
        if (c + 1 < NCH) CP_WAIT1(); else CP_WAIT0();
        __syncthreads();
        if (c + 2 < NCH) {
            uint32_t d = sdst + lstage * STAGE_BYTES;
            const uint4* ag = agl + (size_t)(c + 2) * 8;
            const uint4* bg = bgl + (size_t)(c + 2) * 8;
            #pragma unroll
            for (int p = 0; p < 4; p++) {
                cp16(d + p * 32 * (PAD * 2),              ag + (size_t)p * 32 * ld4);
                cp16(d + TILE_BYTES + p * 32 * (PAD * 2), bg + (size_t)p * 32 * ld4);
            }
            CP_COMMIT();
            if (++lstage == NSTAGE) lstage = 0;
        }
        uint32_t ab = sb + stage * STAGE_BYTES + a_off;
        uint32_t bb = sb + stage * STAGE_BYTES + b_off;
        #pragma unroll
        for (int ks = 0; ks < 4; ks++) {
            uint32_t af[4][4], bf[2][4];
            #pragma unroll
            for (int mt = 0; mt < 4; mt++) ldsm4(af[mt], ab + (mt * 16 * PAD + ks * 16) * 2);
            #pragma unroll
            for (int pr = 0; pr < 2; pr++) ldsm4(bf[pr], bb + (pr * 16 * PAD + ks * 16) * 2);
            #pragma unroll
            for (int mt = 0; mt < 4; mt++) {
                mma_bf16(acc[mt][0], af[mt], &bf[0][0]);
                mma_bf16(acc[mt][1], af[mt], &bf[0][2]);
                mma_bf16(acc[mt][2], af[mt], &bf[1][0]);
                mma_bf16(acc[mt][3], af[mt], &bf[1][2]);
            }
        }
        if (++stage == NSTAGE) stage = 0;
    }

    int crow = lane >> 2, ccol = (lane & 3) * 2;
    #pragma unroll
    for (int mt = 0; mt < 4; mt++) {
        #pragma unroll
        for (int half = 0; half < 2; half++) {
            int m = m0 + warp_m + mt * 16 + crow + half * 8;
            if (m >= M) continue;
            #pragma unroll
            for (int nt = 0; nt < 4; nt++) {
                int n = n0 + warp_n + nt * 8 + ccol;
                float vx = acc[mt][nt][half * 2 + 0];
                float vy = acc[mt][nt][half * 2 + 1];
                if (outp2) {
                    // split-half mode: offsets/logits intermediates
                    if (n < N1) {
                        __half2 hv = __floats2half2_rn(vx + bias[n], vy + bias[n + 1]);
                        *(__half2*)((__half*)outp + (size_t)m * N1 + n) = hv;
                    } else {
                        int S2 = N - N1, n2 = n - N1;
                        __half2 hv = __floats2half2_rn(vx + bias2[n2], vy + bias2[n2 + 1]);
                        *(__half2*)((__half*)outp2 + (size_t)m * S2 + n2) = hv;
                    }
                } else {
                    vx += bias[n]; vy += bias[n + 1];
                    if (residual) {
                        float2 rr = *(const float2*)(residual + (size_t)m * N1 + n);
                        vx = rr.x + gain[n]     * vx;
                        vy = rr.y + gain[n + 1] * vy;
                    }
                    if (outb) {
                        *(__nv_bfloat162*)(outb + (size_t)m * N1 + n) = __floats2bfloat162_rn(vx, vy);
                    } else {
                        *(float2*)(outp + (size_t)m * N1 + n) = make_float2(vx, vy);
                    }
                }
            }
        }
    }
}

// ---------------- fused FFN-up, 3-stage cp.async ring ----------------
#define DTILE_A  (128 * PAD * 2)                    // 18432
#define DTILE_B  (64 * PAD * 2)                     // 9216
#define DSTAGE   (DTILE_A + 2 * DTILE_B)            // 36864

__global__ void __launch_bounds__(256) hmma_dual_kernel(
    const __nv_bfloat16* __restrict__ A,
    const __nv_bfloat16* __restrict__ B1, const float* __restrict__ b1,
    const __nv_bfloat16* __restrict__ B2, const float* __restrict__ b2,
    __nv_bfloat16* __restrict__ outp, int M, int N, int K)
{
    extern __shared__ __align__(16) char smem[];
    uint32_t sb = smem_u32(smem);
    int tid = threadIdx.x, lane = tid & 31, wid = tid >> 5;
    int m0 = blockIdx.y * 128, n0 = blockIdx.x * 64;
    int warp_m = (wid & 1) * 64, warp_n = (wid >> 1) * 16;

    float acc1[4][2][4] = {}, acc2[4][2][4] = {};

    int sub = lane >> 3, lrow = lane & 7;
    uint32_t a_off  = ((warp_m + (sub & 1) * 8 + lrow) * PAD + (sub >> 1) * 8) * 2;
    uint32_t b1_off = DTILE_A + ((warp_n + (sub >> 1) * 8 + lrow) * PAD + (sub & 1) * 8) * 2;
    uint32_t b2_off = DTILE_A + DTILE_B + ((warp_n + (sub >> 1) * 8 + lrow) * PAD + (sub & 1) * 8) * 2;

    const int NCH = K >> 6;
    const int ld4 = K >> 3;
    int lrow4 = tid >> 3, lcol4 = tid & 7;
    const uint4* agl  = (const uint4*)(A  + (size_t)m0 * K) + (size_t)lrow4 * ld4 + lcol4;
    const uint4* bgl1 = (const uint4*)(B1 + (size_t)n0 * K) + (size_t)lrow4 * ld4 + lcol4;
    const uint4* bgl2 = (const uint4*)(B2 + (size_t)n0 * K) + (size_t)lrow4 * ld4 + lcol4;
    uint32_t sdst = sb + lrow4 * (PAD * 2) + lcol4 * 16;
    bool bload = (lrow4 < 64);

    #pragma unroll
    for (int s = 0; s < 2; s++) {
        if (s < NCH) {
            uint32_t d = sdst + s * DSTAGE;
            const uint4* ag = agl + (size_t)s * 8;
            #pragma unroll
            for (int p = 0; p < 4; p++)
                cp16(d + p * 32 * (PAD * 2), ag + (size_t)p * 32 * ld4);
            if (bload) {
                const uint4* bg1 = bgl1 + (size_t)s * 8;
                const uint4* bg2 = bgl2 + (size_t)s * 8;
                cp16(d + DTILE_A,              bg1);
                cp16(d + DTILE_A + 32*(PAD*2), bg1 + (size_t)32 * ld4);
                cp16(d + DTILE_A + DTILE_B,              bg2);
                cp16(d + DTILE_A + DTILE_B + 32*(PAD*2), bg2 + (size_t)32 * ld4);
            }
        }
        CP_COMMIT();
    }

    int stage = 0, lstage = 2;
    for (int c = 0; c < NCH; c++) {
        if (c + 1 < NCH) CP_WAIT1(); else CP_WAIT0();
        __syncthreads();
        if (c + 2 < NCH) {
            uint32_t d = sdst + lstage * DSTAGE;
            const uint4* ag = agl + (size_t)(c + 2) * 8;
            #pragma unroll
            for (int p = 0; p < 4; p++)
                cp16(d + p * 32 * (PAD * 2), ag + (size_t)p * 32 * ld4);
            if (bload) {
                const uint4* bg1 = bgl1 + (size_t)(c + 2) * 8;
                const uint4* bg2 = bgl2 + (size_t)(c + 2) * 8;
                cp16(d + DTILE_A,              bg1);
                cp16(d + DTILE_A + 32*(PAD*2), bg1 + (size_t)32 * ld4);
                cp16(d + DTILE_A + DTILE_B,              bg2);
                cp16(d + DTILE_A + DTILE_B + 32*(PAD*2), bg2 + (size_t)32 * ld4);
            }
            CP_COMMIT();
            if (++lstage == NSTAGE) lstage = 0;
        }
        uint32_t ab  = sb + stage * DSTAGE + a_off;
        uint32_t bb1 = sb + stage * DSTAGE + b1_off;
        uint32_t bb2 = sb + stage * DSTAGE + b2_off;
        #pragma unroll
        for (int ks = 0; ks < 4; ks++) {
            uint32_t af[4][4], bf1[4], bf2[4];
            #pragma unroll
            for (int mt = 0; mt < 4; mt++) ldsm4(af[mt], ab + (mt * 16 * PAD + ks * 16) * 2);
            ldsm4(bf1, bb1 + (ks * 16) * 2);
            ldsm4(bf2, bb2 + (ks * 16) * 2);
            #pragma unroll
            for (int mt = 0; mt < 4; mt++) {
                mma_bf16(acc1[mt][0], af[mt], &bf1[0]);
                mma_bf16(acc1[mt][1], af[mt], &bf1[2]);
                mma_bf16(acc2[mt][0], af[mt], &bf2[0]);
                mma_bf16(acc2[mt][1], af[mt], &bf2[2]);
            }
        }
        if (++stage == NSTAGE) stage = 0;
    }

    int crow = lane >> 2, ccol = (lane & 3) * 2;
    #pragma unroll
    for (int mt = 0; mt < 4; mt++) {
        #pragma unroll
        for (int half = 0; half < 2; half++) {
            int m = m0 + warp_m + mt * 16 + crow + half * 8;
            if (m >= M) continue;
            #pragma unroll
            for (int nt = 0; nt < 2; nt++) {
                int n = n0 + warp_n + nt * 8 + ccol;
                float z0 = acc1[mt][nt][half * 2 + 0] + b1[n];
                float z1 = acc1[mt][nt][half * 2 + 1] + b1[n + 1];
                float g0 = acc2[mt][nt][half * 2 + 0] + b2[n];
                float g1 = acc2[mt][nt][half * 2 + 1] + b2[n + 1];
                float h0 = (z0 / (1.0f + __expf(-z0))) * g0;
                float h1 = (z1 / (1.0f + __expf(-z1))) * g1;
                *(__nv_bfloat162*)(outp + (size_t)m * N + n) = __floats2bfloat162_rn(h0, h1);
            }
        }
    }
}

// ---------------- deformable-attention sampling ----------------
// 8 tokens/block; one warp per token: 8 heads x 4 lanes, each lane 8 channels (uint4).
__global__ void __launch_bounds__(256) msda_kernel(
    const float* __restrict__ ref,
    const __nv_bfloat16* __restrict__ value,
    const __half* __restrict__ off,
    const __half* __restrict__ awl,
    __nv_bfloat16* __restrict__ outp)
{
    int tid   = threadIdx.x;
    int wid   = tid >> 5, lane = tid & 31;
    int token = blockIdx.x * 8 + wid;
    if (token >= MTOK) return;
    int h  = lane >> 2;
    int cg = lane & 3;                         // uint4 group (8 bf16 channels)

    const __half* aw = awl + (size_t)token * 128 + h * 16;
    const __half* of = off + (size_t)token * 256 + h * 32;

    float wgt[16];
    float mx = -1e30f;
    #pragma unroll
    for (int s = 0; s < 16; s++) { wgt[s] = __half2float(aw[s]); mx = fmaxf(mx, wgt[s]); }
    float sum = 0.f;
    #pragma unroll
    for (int s = 0; s < 16; s++) { wgt[s] = __expf(wgt[s] - mx); sum += wgt[s]; }
    float inv = 1.0f / sum;

    int b = token / LQ;
    const uint4* vb = (const uint4*)value + (size_t)b * LQ * 32 + h * 4 + cg;

    float acc[8] = {};
    #pragma unroll
    for (int l = 0; l < 4; l++) {
        const int H  = c_H[l];
        const int W  = c_W[l];
        const int st = c_st[l];
        float rx = ref[(size_t)token * 8 + l * 2 + 0];
        float ry = ref[(size_t)token * 8 + l * 2 + 1];
        #pragma unroll
        for (int p = 0; p < 4; p++) {
            int s = l * 4 + p;
            float x = fmaf(rx, (float)W, __half2float(of[s * 2 + 0]) - 0.5f);
            float y = fmaf(ry, (float)H, __half2float(of[s * 2 + 1]) - 0.5f);
            float x0f = floorf(x), y0f = floorf(y);
            int   x0  = (int)x0f,  y0  = (int)y0f;
            float lx = x - x0f, ly = y - y0f;
            float ws  = wgt[s] * inv;
            float w00 = (1.f - lx) * (1.f - ly) * ws;
            float w01 = lx * (1.f - ly) * ws;
            float w10 = (1.f - lx) * ly * ws;
            float w11 = lx * ly * ws;
            bool x0v = (x0 >= 0)     && (x0 < W);
            bool x1v = (x0 + 1 >= 0) && (x0 + 1 < W);
            #pragma unroll
            for (int dy = 0; dy < 2; dy++) {
                int yy = y0 + dy;
                if (yy < 0 || yy >= H) continue;
                long long base = (long long)(st + yy * W) * 32;
                float wa = dy ? w10 : w00;
                float wb = dy ? w11 : w01;
                if (x0v) {
                    uint4 v = vb[base + (long long)x0 * 32];
                    float2 f0 = __bfloat1622float2(*(__nv_bfloat162*)&v.x);
                    float2 f1 = __bfloat1622float2(*(__nv_bfloat162*)&v.y);
                    float2 f2 = __bfloat1622float2(*(__nv_bfloat162*)&v.z);
                    float2 f3 = __bfloat1622float2(*(__nv_bfloat162*)&v.w);
                    acc[0] += wa * f0.x; acc[1] += wa * f0.y;
                    acc[2] += wa * f1.x; acc[3] += wa * f1.y;
                    acc[4] += wa * f2.x; acc[5] += wa * f2.y;
                    acc[6] += wa * f3.x; acc[7] += wa * f3.y;
                }
                if (x1v) {
                    uint4 v = vb[base + (long long)(x0 + 1) * 32];
                    float2 f0 = __bfloat1622float2(*(__nv_bfloat162*)&v.x);
                    float2 f1 = __bfloat1622float2(*(__nv_bfloat162*)&v.y);
                    float2 f2 = __bfloat1622float2(*(__nv_bfloat162*)&v.z);
                    float2 f3 = __bfloat1622float2(*(__nv_bfloat162*)&v.w);
                    acc[0] += wb * f0.x; acc[1] += wb * f0.y;
                    acc[2] += wb * f1.x; acc[3] += wb * f1.y;
                    acc[4] += wb * f2.x; acc[5] += wb * f2.y;
                    acc[6] += wb * f3.x; acc[7] += wb * f3.y;
                }
            }
        }
    }
    uint4 o;
    *(__nv_bfloat162*)&o.x = __floats2bfloat162_rn(acc[0], acc[1]);
    *(__nv_bfloat162*)&o.y = __floats2bfloat162_rn(acc[2], acc[3]);
    *(__nv_bfloat162*)&o.z = __floats2bfloat162_rn(acc[4], acc[5]);
    *(__nv_bfloat162*)&o.w = __floats2bfloat162_rn(acc[6], acc[7]);
    *(uint4*)(outp + (size_t)token * 256 + h * 32 + cg * 8) = o;
}

// ---------------- host launch ----------------
template <typename T>
static T* symaddr(const void* sym) {
    void* p = nullptr;
    cudaGetSymbolAddress(&p, sym);
    return (T*)p;
}

extern "C" void kernel_launch(void* const* d_in, const int* in_sizes, int n_in,
                              void* d_out, int out_size) {
    (void)in_sizes; (void)n_in; (void)out_size;
    const float* query = (const float*)d_in[0];
    const float* qpos  = (const float*)d_in[1];
    const float* ref   = (const float*)d_in[2];
    const float* nw1   = (const float*)d_in[5];
    const float* Wv    = (const float*)d_in[6];
    const float* bv    = (const float*)d_in[7];
    const float* Woff  = (const float*)d_in[8];
    const float* boff  = (const float*)d_in[9];
    const float* Waw   = (const float*)d_in[10];
    const float* baw   = (const float*)d_in[11];
    const float* Wo    = (const float*)d_in[12];
    const float* bo    = (const float*)d_in[13];
    const float* lsa   = (const float*)d_in[14];
    const float* nw2   = (const float*)d_in[15];
    const float* W1    = (const float*)d_in[16];
    const float* b1    = (const float*)d_in[17];
    const float* W2    = (const float*)d_in[18];
    const float* b2    = (const float*)d_in[19];
    const float* W3    = (const float*)d_in[20];
    const float* b3    = (const float*)d_in[21];
    const float* lsf   = (const float*)d_in[22];
    float* out = (float*)d_out;

    __nv_bfloat16* nb    = symaddr<__nv_bfloat16>(g_nb);
    __nv_bfloat16* qb    = symaddr<__nv_bfloat16>(g_qb);
    __nv_bfloat16* valb  = symaddr<__nv_bfloat16>(g_valueb);
    __half*        poff  = symaddr<__half>(g_off);
    __half*        pawl  = symaddr<__half>(g_awl);
    __nv_bfloat16* attnb = symaddr<__nv_bfloat16>(g_attnb);
    float*         px    = symaddr<float>(g_x);
    __nv_bfloat16* n2b   = symaddr<__nv_bfloat16>(g_n2b);
    __nv_bfloat16* hb    = symaddr<__nv_bfloat16>(g_hb);
    __nv_bfloat16* wb    = symaddr<__nv_bfloat16>(g_wb);

    const int GSM = NSTAGE * STAGE_BYTES;   // 110592
    const int DSM = NSTAGE * DSTAGE;        // 110592
    cudaFuncSetAttribute(hmma_gemm_kernel, cudaFuncAttributeMaxDynamicSharedMemorySize, GSM);
    cudaFuncSetAttribute(hmma_dual_kernel, cudaFuncAttributeMaxDynamicSharedMemorySize, DSM);

    // 0. weights -> bf16
    WSrc ws; ws.s[0] = Wv; ws.s[1] = Woff; ws.s[2] = Waw; ws.s[3] = Wo;
    ws.s[4] = W1; ws.s[5] = W2; ws.s[6] = W3;
    wconv_kernel<<<dim3(256, 7), 256>>>(ws);

    // 1. rmsnorm -> normed bf16, q = normed+pos bf16
    rmsnorm_kernel<<<(MTOK + 7) / 8, 256>>>(query, nw1, nb, qpos, qb);
    // 2. value = normed @ Wv^T + bv  (bf16 out)
    hmma_gemm_kernel<<<dim3(2, MT128), 256, GSM>>>(nb, wb + WOFF_WV, bv, nullptr,
        nullptr, nullptr, valb, MTOK, 256, 256, 256, nullptr, nullptr);
    // 3. fused offsets+logits: q @ [Woff;Waw]^T, split fp16 outputs
    hmma_gemm_kernel<<<dim3(3, MT128), 256, GSM>>>(qb, wb + WOFF_WOFF, boff, baw,
        (float*)poff, (float*)pawl, nullptr, MTOK, 384, 256, 256, nullptr, nullptr);
    // 4. deformable sampling -> attn bf16 (8 tokens/block, warp/token)
    msda_kernel<<<(MTOK + 7) / 8, 256>>>(ref, valb, poff, pawl, attnb);
    // 5. x = query + ls_attn * (attn @ Wo^T + bo)
    hmma_gemm_kernel<<<dim3(2, MT128), 256, GSM>>>(attnb, wb + WOFF_WO, bo, nullptr,
        px, nullptr, nullptr, MTOK, 256, 256, 256, query, lsa);
    // 6. n2 = rmsnorm(x) bf16
    rmsnorm_kernel<<<(MTOK + 7) / 8, 256>>>(px, nw2, n2b, nullptr, nullptr);
    // 7. h = silu(n2@W1^T+b1)*(n2@W2^T+b2) bf16
    hmma_dual_kernel<<<dim3(16, MT128), 256, DSM>>>(n2b, wb + WOFF_W1, b1, wb + WOFF_W2, b2, hb, MTOK, DFFN, 256);
    // 8. out = x + ls_ffn * (h @ W3^T + b3)
    hmma_gemm_kernel<<<dim3(2, MT128), 256, GSM>>>(hb, wb + WOFF_W3, b3, nullptr,
        out, nullptr, nullptr, MTOK, 256, 256, 1024, px, lsf);
}

// round 10
// speedup vs baseline: 1.6020x; 1.0964x over previous
#include <cuda_runtime.h>
#include <cuda_bf16.h>
#include <cuda_fp16.h>
#include <cuda_fp8.h>
#include <cstdint>
#include <math.h>

// ---------------- problem constants ----------------
#define BSZ   2
#define LQ    17821
#define CDIM  256
#define MTOK  (BSZ*LQ)          // 35642
#define MPAD  35712             // 279 * 128
#define MT128 279
#define DFFN  1024
#define PAD   72                // smem row stride in halves (144B, conflict-free)

__device__ __constant__ int c_H[4]  = {100, 50, 25, 13};
__device__ __constant__ int c_W[4]  = {134, 67, 34, 17};
__device__ __constant__ int c_st[4] = {0, 13400, 16750, 17600};

// ---------------- scratch (no allocs; zero-initialized .bss) ----------------
__device__ __nv_bfloat16 g_nb    [(size_t)MPAD*CDIM];
__device__ __nv_bfloat16 g_qb    [(size_t)MPAD*CDIM];
__device__ unsigned char g_value8[(size_t)MPAD*CDIM];   // fp8 e4m3 value tensor
__device__ __half        g_off   [(size_t)MTOK*CDIM];
__device__ __half        g_awl   [(size_t)MTOK*128];
__device__ __nv_bfloat16 g_attnb [(size_t)MPAD*CDIM];
__device__ float         g_x     [(size_t)MTOK*CDIM];
__device__ __nv_bfloat16 g_n2b   [(size_t)MPAD*CDIM];
__device__ __nv_bfloat16 g_hb    [(size_t)MPAD*DFFN];
// converted weights: Wv,Woff,Waw,Wo,W1,W2,W3
#define WOFF_WV   0
#define WOFF_WOFF 65536
#define WOFF_WAW  131072
#define WOFF_WO   163840
#define WOFF_W1   229376
#define WOFF_W2   491520
#define WOFF_W3   753664
__device__ __nv_bfloat16 g_wb[1015808];

// ================= helpers =================
__device__ __forceinline__ uint32_t smem_u32(const void* p) {
    uint32_t a;
    asm("{ .reg .u64 t; cvta.to.shared.u64 t, %1; cvt.u32.u64 %0, t; }" : "=r"(a) : "l"(p));
    return a;
}
__device__ __forceinline__ void ldsm4(uint32_t* r, uint32_t addr) {
    asm volatile("ldmatrix.sync.aligned.m8n8.x4.shared.b16 {%0,%1,%2,%3}, [%4];"
        : "=r"(r[0]), "=r"(r[1]), "=r"(r[2]), "=r"(r[3]) : "r"(addr));
}
__device__ __forceinline__ void mma_bf16(float* c, const uint32_t* a, const uint32_t* b) {
    asm volatile(
        "mma.sync.aligned.m16n8k16.row.col.f32.bf16.bf16.f32 "
        "{%0,%1,%2,%3}, {%4,%5,%6,%7}, {%8,%9}, {%0,%1,%2,%3};"
        : "+f"(c[0]), "+f"(c[1]), "+f"(c[2]), "+f"(c[3])
        : "r"(a[0]), "r"(a[1]), "r"(a[2]), "r"(a[3]), "r"(b[0]), "r"(b[1]));
}
__device__ __forceinline__ void cp16(uint32_t dst, const void* src) {
    asm volatile("cp.async.ca.shared.global [%0], [%1], 16;" :: "r"(dst), "l"(src));
}
#define CP_COMMIT() asm volatile("cp.async.commit_group;" ::: "memory")
#define CP_WAIT1()  asm volatile("cp.async.wait_group 1;" ::: "memory")
#define CP_WAIT0()  asm volatile("cp.async.wait_group 0;" ::: "memory")

__device__ __forceinline__ __half2 fp8x2_to_h2(unsigned short s) {
    __half2_raw r = __nv_cvt_fp8x2_to_halfraw2((__nv_fp8x2_storage_t)s, __NV_E4M3);
    return *(__half2*)&r;
}

// ---------------- weight fp32 -> bf16 convert ----------------
struct WSrc { const float* s[7]; };
__device__ __constant__ int c_wsz [7] = {65536, 65536, 32768, 65536, 262144, 262144, 262144};
__device__ __constant__ int c_woff[7] = {WOFF_WV, WOFF_WOFF, WOFF_WAW, WOFF_WO, WOFF_W1, WOFF_W2, WOFF_W3};

__global__ void __launch_bounds__(256) wconv_kernel(WSrc w) {
    int seg = blockIdx.y;
    int i = (blockIdx.x * 256 + threadIdx.x) * 4;
    if (i >= c_wsz[seg]) return;
    float4 v = *(const float4*)(w.s[seg] + i);
    __nv_bfloat16* d = g_wb + c_woff[seg] + i;
    *(__nv_bfloat162*)(d)     = __floats2bfloat162_rn(v.x, v.y);
    *(__nv_bfloat162*)(d + 2) = __floats2bfloat162_rn(v.z, v.w);
}

// ---------------- RMSNorm -> bf16 (+ optional bf16 normed+addend) ----------------
__global__ void __launch_bounds__(256) rmsnorm_kernel(
    const float* __restrict__ x, const float* __restrict__ w,
    __nv_bfloat16* __restrict__ out, const float* __restrict__ addend,
    __nv_bfloat16* __restrict__ out2)
{
    int row  = blockIdx.x * 8 + (threadIdx.x >> 5);
    if (row >= MTOK) return;
    int lane = threadIdx.x & 31;
    const float4* xr = (const float4*)(x + (size_t)row * CDIM);
    float4 v0 = xr[lane];
    float4 v1 = xr[lane + 32];
    float ss = v0.x*v0.x + v0.y*v0.y + v0.z*v0.z + v0.w*v0.w
             + v1.x*v1.x + v1.y*v1.y + v1.z*v1.z + v1.w*v1.w;
    #pragma unroll
    for (int o = 16; o > 0; o >>= 1) ss += __shfl_xor_sync(0xffffffffu, ss, o);
    float s = rsqrtf(ss * (1.0f / CDIM) + 1e-6f);
    const float4* w4 = (const float4*)w;
    float4 g0 = w4[lane], g1 = w4[lane + 32];
    float n0x = v0.x*s*g0.x, n0y = v0.y*s*g0.y, n0z = v0.z*s*g0.z, n0w = v0.w*s*g0.w;
    float n1x = v1.x*s*g1.x, n1y = v1.y*s*g1.y, n1z = v1.z*s*g1.z, n1w = v1.w*s*g1.w;
    __nv_bfloat162* o2 = (__nv_bfloat162*)(out + (size_t)row * CDIM);
    o2[lane*2+0]  = __floats2bfloat162_rn(n0x, n0y);
    o2[lane*2+1]  = __floats2bfloat162_rn(n0z, n0w);
    o2[64+lane*2] = __floats2bfloat162_rn(n1x, n1y);
    o2[65+lane*2] = __floats2bfloat162_rn(n1z, n1w);
    if (out2) {
        const float4* a4 = (const float4*)(addend + (size_t)row * CDIM);
        float4 p0 = a4[lane], p1 = a4[lane + 32];
        __nv_bfloat162* q2 = (__nv_bfloat162*)(out2 + (size_t)row * CDIM);
        q2[lane*2+0]  = __floats2bfloat162_rn(n0x + p0.x, n0y + p0.y);
        q2[lane*2+1]  = __floats2bfloat162_rn(n0z + p0.z, n0w + p0.w);
        q2[64+lane*2] = __floats2bfloat162_rn(n1x + p1.x, n1y + p1.y);
        q2[65+lane*2] = __floats2bfloat162_rn(n1z + p1.z, n1w + p1.w);
    }
}

// ---------------- HMMA GEMM, 3-stage cp.async ring ----------------
// out[m,n] = sum_k A[m,k]*B[n,k] + bias[n].
// Modes: outp2 != null -> split fp16 (n<N1 -> outp as half*, else outp2 as half*)
//        out8  != null -> fp8 e4m3 output
//        outb  != null -> bf16 output
//        else          -> fp32 outp, optional residual+gain
// CTA tile 128x128, 8 warps (each 64x32), K chunk 64.
#define TILE_BYTES  (128 * PAD * 2)     // 18432
#define STAGE_BYTES (2 * TILE_BYTES)    // 36864: [As | Bs]
#define NSTAGE 3

__global__ void __launch_bounds__(256) hmma_gemm_kernel(
    const __nv_bfloat16* __restrict__ A, const __nv_bfloat16* __restrict__ B,
    const float* __restrict__ bias, const float* __restrict__ bias2,
    float* __restrict__ outp, float* __restrict__ outp2,
    __nv_bfloat16* __restrict__ outb, unsigned char* __restrict__ out8,
    int M, int N, int N1, int K,
    const float* __restrict__ residual, const float* __restrict__ gain)
{
    extern __shared__ __align__(16) char smem[];
    uint32_t sb = smem_u32(smem);
    int tid = threadIdx.x, lane = tid & 31, wid = tid >> 5;
    int m0 = blockIdx.y * 128, n0 = blockIdx.x * 128;
    int warp_m = (wid & 1) * 64, warp_n = (wid >> 1) * 32;

    float acc[4][4][4] = {};

    int sub = lane >> 3, lrow = lane & 7;
    uint32_t a_off = ((warp_m + (sub & 1) * 8 + lrow) * PAD + (sub >> 1) * 8) * 2;
    uint32_t b_off = TILE_BYTES + ((warp_n + (sub >> 1) * 8 + lrow) * PAD + (sub & 1) * 8) * 2;

    const int NCH = K >> 6;
    const int ld4 = K >> 3;
    int lrow4 = tid >> 3, lcol4 = tid & 7;
    const uint4* agl = (const uint4*)(A + (size_t)m0 * K) + (size_t)lrow4 * ld4 + lcol4;
    const uint4* bgl = (const uint4*)(B + (size_t)n0 * K) + (size_t)lrow4 * ld4 + lcol4;
    uint32_t sdst = sb + lrow4 * (PAD * 2) + lcol4 * 16;

    #pragma unroll
    for (int s = 0; s < 2; s++) {
        if (s < NCH) {
            uint32_t d = sdst + s * STAGE_BYTES;
            const uint4* ag = agl + (size_t)s * 8;
            const uint4* bg = bgl + (size_t)s * 8;
            #pragma unroll
            for (int p = 0; p < 4; p++) {
                cp16(d + p * 32 * (PAD * 2),              ag + (size_t)p * 32 * ld4);
                cp16(d + TILE_BYTES + p * 32 * (PAD * 2), bg + (size_t)p * 32 * ld4);
            }
        }
        CP_COMMIT();
    }

    int stage = 0, lstage = 2;
    for (int c = 0; c < NCH; c++) {
        if (c + 1 < NCH) CP_WAIT1(); else CP_WAIT0();
        __syncthreads();
        if (c + 2 < NCH) {
            uint32_t d = sdst + lstage * STAGE_BYTES;
            const uint4* ag = agl + (size_t)(c + 2) * 8;
            const uint4* bg = bgl + (size_t)(c + 2) * 8;
            #pragma unroll
            for (int p = 0; p < 4; p++) {
                cp16(d + p * 32 * (PAD * 2),              ag + (size_t)p * 32 * ld4);
                cp16(d + TILE_BYTES + p * 32 * (PAD * 2), bg + (size_t)p * 32 * ld4);
            }
            CP_COMMIT();
            if (++lstage == NSTAGE) lstage = 0;
        }
        uint32_t ab = sb + stage * STAGE_BYTES + a_off;
        uint32_t bb = sb + stage * STAGE_BYTES + b_off;
        #pragma unroll
        for (int ks = 0; ks < 4; ks++) {
            uint32_t af[4][4], bf[2][4];
            #pragma unroll
            for (int mt = 0; mt < 4; mt++) ldsm4(af[mt], ab + (mt * 16 * PAD + ks * 16) * 2);
            #pragma unroll
            for (int pr = 0; pr < 2; pr++) ldsm4(bf[pr], bb + (pr * 16 * PAD + ks * 16) * 2);
            #pragma unroll
            for (int mt = 0; mt < 4; mt++) {
                mma_bf16(acc[mt][0], af[mt], &bf[0][0]);
                mma_bf16(acc[mt][1], af[mt], &bf[0][2]);
                mma_bf16(acc[mt][2], af[mt], &bf[1][0]);
                mma_bf16(acc[mt][3], af[mt], &bf[1][2]);
            }
        }
        if (++stage == NSTAGE) stage = 0;
    }

    int crow = lane >> 2, ccol = (lane & 3) * 2;
    #pragma unroll
    for (int mt = 0; mt < 4; mt++) {
        #pragma unroll
        for (int half = 0; half < 2; half++) {
            int m = m0 + warp_m + mt * 16 + crow + half * 8;
            if (m >= M) continue;
            #pragma unroll
            for (int nt = 0; nt < 4; nt++) {
                int n = n0 + warp_n + nt * 8 + ccol;
                float vx = acc[mt][nt][half * 2 + 0];
                float vy = acc[mt][nt][half * 2 + 1];
                if (outp2) {
                    // split-half mode: offsets/logits intermediates (fp16)
                    if (n < N1) {
                        __half2 hv = __floats2half2_rn(vx + bias[n], vy + bias[n + 1]);
                        *(__half2*)((__half*)outp + (size_t)m * N1 + n) = hv;
                    } else {
                        int S2 = N - N1, n2 = n - N1;
                        __half2 hv = __floats2half2_rn(vx + bias2[n2], vy + bias2[n2 + 1]);
                        *(__half2*)((__half*)outp2 + (size_t)m * S2 + n2) = hv;
                    }
                } else {
                    vx += bias[n]; vy += bias[n + 1];
                    if (residual) {
                        float2 rr = *(const float2*)(residual + (size_t)m * N1 + n);
                        vx = rr.x + gain[n]     * vx;
                        vy = rr.y + gain[n + 1] * vy;
                    }
                    if (out8) {
                        __nv_fp8x2_storage_t p8 = __nv_cvt_float2_to_fp8x2(
                            make_float2(vx, vy), __NV_SATFINITE, __NV_E4M3);
                        *(unsigned short*)(out8 + (size_t)m * N1 + n) = (unsigned short)p8;
                    } else if (outb) {
                        *(__nv_bfloat162*)(outb + (size_t)m * N1 + n) = __floats2bfloat162_rn(vx, vy);
                    } else {
                        *(float2*)(outp + (size_t)m * N1 + n) = make_float2(vx, vy);
                    }
                }
            }
        }
    }
}

// ---------------- fused FFN-up, 3-stage cp.async ring ----------------
#define DTILE_A  (128 * PAD * 2)                    // 18432
#define DTILE_B  (64 * PAD * 2)                     // 9216
#define DSTAGE   (DTILE_A + 2 * DTILE_B)            // 36864

__global__ void __launch_bounds__(256) hmma_dual_kernel(
    const __nv_bfloat16* __restrict__ A,
    const __nv_bfloat16* __restrict__ B1, const float* __restrict__ b1,
    const __nv_bfloat16* __restrict__ B2, const float* __restrict__ b2,
    __nv_bfloat16* __restrict__ outp, int M, int N, int K)
{
    extern __shared__ __align__(16) char smem[];
    uint32_t sb = smem_u32(smem);
    int tid = threadIdx.x, lane = tid & 31, wid = tid >> 5;
    int m0 = blockIdx.y * 128, n0 = blockIdx.x * 64;
    int warp_m = (wid & 1) * 64, warp_n = (wid >> 1) * 16;

    float acc1[4][2][4] = {}, acc2[4][2][4] = {};

    int sub = lane >> 3, lrow = lane & 7;
    uint32_t a_off  = ((warp_m + (sub & 1) * 8 + lrow) * PAD + (sub >> 1) * 8) * 2;
    uint32_t b1_off = DTILE_A + ((warp_n + (sub >> 1) * 8 + lrow) * PAD + (sub & 1) * 8) * 2;
    uint32_t b2_off = DTILE_A + DTILE_B + ((warp_n + (sub >> 1) * 8 + lrow) * PAD + (sub & 1) * 8) * 2;

    const int NCH = K >> 6;
    const int ld4 = K >> 3;
    int lrow4 = tid >> 3, lcol4 = tid & 7;
    const uint4* agl  = (const uint4*)(A  + (size_t)m0 * K) + (size_t)lrow4 * ld4 + lcol4;
    const uint4* bgl1 = (const uint4*)(B1 + (size_t)n0 * K) + (size_t)lrow4 * ld4 + lcol4;
    const uint4* bgl2 = (const uint4*)(B2 + (size_t)n0 * K) + (size_t)lrow4 * ld4 + lcol4;
    uint32_t sdst = sb + lrow4 * (PAD * 2) + lcol4 * 16;
    bool bload = (lrow4 < 64);

    #pragma unroll
    for (int s = 0; s < 2; s++) {
        if (s < NCH) {
            uint32_t d = sdst + s * DSTAGE;
            const uint4* ag = agl + (size_t)s * 8;
            #pragma unroll
            for (int p = 0; p < 4; p++)
                cp16(d + p * 32 * (PAD * 2), ag + (size_t)p * 32 * ld4);
            if (bload) {
                const uint4* bg1 = bgl1 + (size_t)s * 8;
                const uint4* bg2 = bgl2 + (size_t)s * 8;
                cp16(d + DTILE_A,              bg1);
                cp16(d + DTILE_A + 32*(PAD*2), bg1 + (size_t)32 * ld4);
                cp16(d + DTILE_A + DTILE_B,              bg2);
                cp16(d + DTILE_A + DTILE_B + 32*(PAD*2), bg2 + (size_t)32 * ld4);
            }
        }
        CP_COMMIT();
    }

    int stage = 0, lstage = 2;
    for (int c = 0; c < NCH; c++) {
        if (c + 1 < NCH) CP_WAIT1(); else CP_WAIT0();
        __syncthreads();
        if (c + 2 < NCH) {
            uint32_t d = sdst + lstage * DSTAGE;
            const uint4* ag = agl + (size_t)(c + 2) * 8;
            #pragma unroll
            for (int p = 0; p < 4; p++)
                cp16(d + p * 32 * (PAD * 2), ag + (size_t)p * 32 * ld4);
            if (bload) {
                const uint4* bg1 = bgl1 + (size_t)(c + 2) * 8;
                const uint4* bg2 = bgl2 + (size_t)(c + 2) * 8;
                cp16(d + DTILE_A,              bg1);
                cp16(d + DTILE_A + 32*(PAD*2), bg1 + (size_t)32 * ld4);
                cp16(d + DTILE_A + DTILE_B,              bg2);
                cp16(d + DTILE_A + DTILE_B + 32*(PAD*2), bg2 + (size_t)32 * ld4);
            }
            CP_COMMIT();
            if (++lstage == NSTAGE) lstage = 0;
        }
        uint32_t ab  = sb + stage * DSTAGE + a_off;
        uint32_t bb1 = sb + stage * DSTAGE + b1_off;
        uint32_t bb2 = sb + stage * DSTAGE + b2_off;
        #pragma unroll
        for (int ks = 0; ks < 4; ks++) {
            uint32_t af[4][4], bf1[4], bf2[4];
            #pragma unroll
            for (int mt = 0; mt < 4; mt++) ldsm4(af[mt], ab + (mt * 16 * PAD + ks * 16) * 2);
            ldsm4(bf1, bb1 + (ks * 16) * 2);
            ldsm4(bf2, bb2 + (ks * 16) * 2);
            #pragma unroll
            for (int mt = 0; mt < 4; mt++) {
                mma_bf16(acc1[mt][0], af[mt], &bf1[0]);
                mma_bf16(acc1[mt][1], af[mt], &bf1[2]);
                mma_bf16(acc2[mt][0], af[mt], &bf2[0]);
                mma_bf16(acc2[mt][1], af[mt], &bf2[2]);
            }
        }
        if (++stage == NSTAGE) stage = 0;
    }

    int crow = lane >> 2, ccol = (lane & 3) * 2;
    #pragma unroll
    for (int mt = 0; mt < 4; mt++) {
        #pragma unroll
        for (int half = 0; half < 2; half++) {
            int m = m0 + warp_m + mt * 16 + crow + half * 8;
            if (m >= M) continue;
            #pragma unroll
            for (int nt = 0; nt < 2; nt++) {
                int n = n0 + warp_n + nt * 8 + ccol;
                float z0 = acc1[mt][nt][half * 2 + 0] + b1[n];
                float z1 = acc1[mt][nt][half * 2 + 1] + b1[n + 1];
                float g0 = acc2[mt][nt][half * 2 + 0] + b2[n];
                float g1 = acc2[mt][nt][half * 2 + 1] + b2[n + 1];
                float h0 = (z0 / (1.0f + __expf(-z0))) * g0;
                float h1 = (z1 / (1.0f + __expf(-z1))) * g1;
                *(__nv_bfloat162*)(outp + (size_t)m * N + n) = __floats2bfloat162_rn(h0, h1);
            }
        }
    }
}

// ---------------- deformable-attention sampling (fp8 value) ----------------
// 8 tokens/block; one warp per token: 8 heads x 4 lanes, each lane 8 fp8 channels (uint2).
__global__ void __launch_bounds__(256) msda_kernel(
    const float* __restrict__ ref,
    const unsigned char* __restrict__ value,
    const __half* __restrict__ off,
    const __half* __restrict__ awl,
    __nv_bfloat16* __restrict__ outp)
{
    int tid   = threadIdx.x;
    int wid   = tid >> 5, lane = tid & 31;
    int token = blockIdx.x * 8 + wid;
    if (token >= MTOK) return;
    int h  = lane >> 2;
    int cg = lane & 3;                         // uint2 group (8 fp8 channels)

    const __half* aw = awl + (size_t)token * 128 + h * 16;
    const __half* of = off + (size_t)token * 256 + h * 32;

    float wgt[16];
    float mx = -1e30f;
    #pragma unroll
    for (int s = 0; s < 16; s++) { wgt[s] = __half2float(aw[s]); mx = fmaxf(mx, wgt[s]); }
    float sum = 0.f;
    #pragma unroll
    for (int s = 0; s < 16; s++) { wgt[s] = __expf(wgt[s] - mx); sum += wgt[s]; }
    float inv = 1.0f / sum;

    int b = token / LQ;
    const uint2* vb = (const uint2*)(value + (size_t)b * LQ * 256) + h * 4 + cg;

    __half2 acch[4] = {__half2(0,0), __half2(0,0), __half2(0,0), __half2(0,0)};
    #pragma unroll
    for (int l = 0; l < 4; l++) {
        const int H  = c_H[l];
        const int W  = c_W[l];
        const int st = c_st[l];
        float rx = ref[(size_t)token * 8 + l * 2 + 0];
        float ry = ref[(size_t)token * 8 + l * 2 + 1];
        #pragma unroll
        for (int p = 0; p < 4; p++) {
            int s = l * 4 + p;
            float x = fmaf(rx, (float)W, __half2float(of[s * 2 + 0]) - 0.5f);
            float y = fmaf(ry, (float)H, __half2float(of[s * 2 + 1]) - 0.5f);
            float x0f = floorf(x), y0f = floorf(y);
            int   x0  = (int)x0f,  y0  = (int)y0f;
            float lx = x - x0f, ly = y - y0f;
            float ws  = wgt[s] * inv;
            float w00 = (1.f - lx) * (1.f - ly) * ws;
            float w01 = lx * (1.f - ly) * ws;
            float w10 = (1.f - lx) * ly * ws;
            float w11 = lx * ly * ws;
            bool x0v = (x0 >= 0)     && (x0 < W);
            bool x1v = (x0 + 1 >= 0) && (x0 + 1 < W);
            #pragma unroll
            for (int dy = 0; dy < 2; dy++) {
                int yy = y0 + dy;
                if (yy < 0 || yy >= H) continue;
                long long base = (long long)(st + yy * W) * 32;
                float wa = dy ? w10 : w00;
                float wb = dy ? w11 : w01;
                if (x0v) {
                    uint2 v = vb[base + (long long)x0 * 32];
                    __half2 wh = __float2half2_rn(wa);
                    acch[0] = __hfma2(fp8x2_to_h2(v.x & 0xFFFFu),  wh, acch[0]);
                    acch[1] = __hfma2(fp8x2_to_h2(v.x >> 16),      wh, acch[1]);
                    acch[2] = __hfma2(fp8x2_to_h2(v.y & 0xFFFFu),  wh, acch[2]);
                    acch[3] = __hfma2(fp8x2_to_h2(v.y >> 16),      wh, acch[3]);
                }
                if (x1v) {
                    uint2 v = vb[base + (long long)(x0 + 1) * 32];
                    __half2 wh = __float2half2_rn(wb);
                    acch[0] = __hfma2(fp8x2_to_h2(v.x & 0xFFFFu),  wh, acch[0]);
                    acch[1] = __hfma2(fp8x2_to_h2(v.x >> 16),      wh, acch[1]);
                    acch[2] = __hfma2(fp8x2_to_h2(v.y & 0xFFFFu),  wh, acch[2]);
                    acch[3] = __hfma2(fp8x2_to_h2(v.y >> 16),      wh, acch[3]);
                }
            }
        }
    }
    uint4 o;
    float2 f0 = __half22float2(acch[0]);
    float2 f1 = __half22float2(acch[1]);
    float2 f2 = __half22float2(acch[2]);
    float2 f3 = __half22float2(acch[3]);
    *(__nv_bfloat162*)&o.x = __floats2bfloat162_rn(f0.x, f0.y);
    *(__nv_bfloat162*)&o.y = __floats2bfloat162_rn(f1.x, f1.y);
    *(__nv_bfloat162*)&o.z = __floats2bfloat162_rn(f2.x, f2.y);
    *(__nv_bfloat162*)&o.w = __floats2bfloat162_rn(f3.x, f3.y);
    *(uint4*)(outp + (size_t)token * 256 + h * 32 + cg * 8) = o;
}

// ---------------- host launch ----------------
template <typename T>
static T* symaddr(const void* sym) {
    void* p = nullptr;
    cudaGetSymbolAddress(&p, sym);
    return (T*)p;
}

extern "C" void kernel_launch(void* const* d_in, const int* in_sizes, int n_in,
                              void* d_out, int out_size) {
    (void)in_sizes; (void)n_in; (void)out_size;
    const float* query = (const float*)d_in[0];
    const float* qpos  = (const float*)d_in[1];
    const float* ref   = (const float*)d_in[2];
    const float* nw1   = (const float*)d_in[5];
    const float* Wv    = (const float*)d_in[6];
    const float* bv    = (const float*)d_in[7];
    const float* Woff  = (const float*)d_in[8];
    const float* boff  = (const float*)d_in[9];
    const float* Waw   = (const float*)d_in[10];
    const float* baw   = (const float*)d_in[11];
    const float* Wo    = (const float*)d_in[12];
    const float* bo    = (const float*)d_in[13];
    const float* lsa   = (const float*)d_in[14];
    const float* nw2   = (const float*)d_in[15];
    const float* W1    = (const float*)d_in[16];
    const float* b1    = (const float*)d_in[17];
    const float* W2    = (const float*)d_in[18];
    const float* b2    = (const float*)d_in[19];
    const float* W3    = (const float*)d_in[20];
    const float* b3    = (const float*)d_in[21];
    const float* lsf   = (const float*)d_in[22];
    float* out = (float*)d_out;

    __nv_bfloat16* nb    = symaddr<__nv_bfloat16>(g_nb);
    __nv_bfloat16* qb    = symaddr<__nv_bfloat16>(g_qb);
    unsigned char* val8  = symaddr<unsigned char>(g_value8);
    __half*        poff  = symaddr<__half>(g_off);
    __half*        pawl  = symaddr<__half>(g_awl);
    __nv_bfloat16* attnb = symaddr<__nv_bfloat16>(g_attnb);
    float*         px    = symaddr<float>(g_x);
    __nv_bfloat16* n2b   = symaddr<__nv_bfloat16>(g_n2b);
    __nv_bfloat16* hb    = symaddr<__nv_bfloat16>(g_hb);
    __nv_bfloat16* wb    = symaddr<__nv_bfloat16>(g_wb);

    const int GSM = NSTAGE * STAGE_BYTES;   // 110592
    const int DSM = NSTAGE * DSTAGE;        // 110592
    cudaFuncSetAttribute(hmma_gemm_kernel, cudaFuncAttributeMaxDynamicSharedMemorySize, GSM);
    cudaFuncSetAttribute(hmma_dual_kernel, cudaFuncAttributeMaxDynamicSharedMemorySize, DSM);

    // 0. weights -> bf16
    WSrc ws; ws.s[0] = Wv; ws.s[1] = Woff; ws.s[2] = Waw; ws.s[3] = Wo;
    ws.s[4] = W1; ws.s[5] = W2; ws.s[6] = W3;
    wconv_kernel<<<dim3(256, 7), 256>>>(ws);

    // 1. rmsnorm -> normed bf16, q = normed+pos bf16
    rmsnorm_kernel<<<(MTOK + 7) / 8, 256>>>(query, nw1, nb, qpos, qb);
    // 2. value = normed @ Wv^T + bv  (fp8 out)
    hmma_gemm_kernel<<<dim3(2, MT128), 256, GSM>>>(nb, wb + WOFF_WV, bv, nullptr,
        nullptr, nullptr, nullptr, val8, MTOK, 256, 256, 256, nullptr, nullptr);
    // 3. fused offsets+logits: q @ [Woff;Waw]^T, split fp16 outputs
    hmma_gemm_kernel<<<dim3(3, MT128), 256, GSM>>>(qb, wb + WOFF_WOFF, boff, baw,
        (float*)poff, (float*)pawl, nullptr, nullptr, MTOK, 384, 256, 256, nullptr, nullptr);
    // 4. deformable sampling -> attn bf16 (warp/token, fp8 gathers)
    msda_kernel<<<(MTOK + 7) / 8, 256>>>(ref, val8, poff, pawl, attnb);
    // 5. x = query + ls_attn * (attn @ Wo^T + bo)
    hmma_gemm_kernel<<<dim3(2, MT128), 256, GSM>>>(attnb, wb + WOFF_WO, bo, nullptr,
        px, nullptr, nullptr, nullptr, MTOK, 256, 256, 256, query, lsa);
    // 6. n2 = rmsnorm(x) bf16
    rmsnorm_kernel<<<(MTOK + 7) / 8, 256>>>(px, nw2, n2b, nullptr, nullptr);
    // 7. h = silu(n2@W1^T+b1)*(n2@W2^T+b2) bf16
    hmma_dual_kernel<<<dim3(16, MT128), 256, DSM>>>(n2b, wb + WOFF_W1, b1, wb + WOFF_W2, b2, hb, MTOK, DFFN, 256);
    // 8. out = x + ls_ffn * (h @ W3^T + b3)
    hmma_gemm_kernel<<<dim3(2, MT128), 256, GSM>>>(hb, wb + WOFF_W3, b3, nullptr,
        out, nullptr, nullptr, nullptr, MTOK, 256, 256, 1024, px, lsf);
}